// round 3
// baseline (speedup 1.0000x reference)
#include <cuda_runtime.h>

#define NU 50000
#define NI 50000
#define NN 100000
#define DIM 64
#define EMAX 2000000
#define FW 192              // combined feature width: 3 stacks x 64
#define FW2 96              // in float2 units
#define NB_SCAN 196         // 196*512 >= 100000

// ---------------- device scratch (static; no dynamic allocation) -------------
__device__ int   g_deg[NN];
__device__ float g_dinv[NN];
__device__ int   g_rowptr[NN];
__device__ int   g_cursor[NN];
__device__ int2  g_edges[2 * EMAX];          // (src, bitcast(dinv[src])) per directed edge
__device__ float g_X[(size_t)NN * FW];       // current layer input  (76.8 MB)
__device__ float g_H[(size_t)NN * FW];       // x @ W.T              (76.8 MB)
__device__ float g_ACC[(size_t)NN * FW];     // running sum          (76.8 MB)
__device__ int   g_partial[NB_SCAN];

// ---------------- graph build ------------------------------------------------
__global__ void k_deg_init() {
    int n = blockIdx.x * blockDim.x + threadIdx.x;
    if (n < NN) g_deg[n] = 1;                 // self loop
}

__global__ void k_count(const int* __restrict__ ei, int E) {
    int e = blockIdx.x * blockDim.x + threadIdx.x;
    if (e >= E) return;
    int u = ei[2 * e];
    int it = ei[2 * e + 1] + NU;
    atomicAdd(&g_deg[u], 1);
    atomicAdd(&g_deg[it], 1);
}

__global__ void k_dinv() {
    int n = blockIdx.x * blockDim.x + threadIdx.x;
    if (n < NN) g_dinv[n] = rsqrtf((float)g_deg[n]);
}

// neighbor count per node = deg-1 (self loop handled analytically)
__global__ void k_scan1() {
    __shared__ int sh[512];
    int t = threadIdx.x;
    int idx = blockIdx.x * 512 + t;
    int v = (idx < NN) ? (g_deg[idx] - 1) : 0;
    sh[t] = v;
    __syncthreads();
    for (int off = 256; off > 0; off >>= 1) {
        if (t < off) sh[t] += sh[t + off];
        __syncthreads();
    }
    if (t == 0) g_partial[blockIdx.x] = sh[0];
}

__global__ void k_scan2() {
    int run = 0;
    for (int b = 0; b < NB_SCAN; ++b) {
        int v = g_partial[b];
        g_partial[b] = run;
        run += v;
    }
}

__global__ void k_scan3() {
    __shared__ int sh[512];
    int t = threadIdx.x;
    int idx = blockIdx.x * 512 + t;
    int v = (idx < NN) ? (g_deg[idx] - 1) : 0;
    sh[t] = v;
    __syncthreads();
    for (int off = 1; off < 512; off <<= 1) {
        int x = (t >= off) ? sh[t - off] : 0;
        __syncthreads();
        sh[t] += x;
        __syncthreads();
    }
    if (idx < NN) {
        int excl = g_partial[blockIdx.x] + sh[t] - v;
        g_rowptr[idx] = excl;
        g_cursor[idx] = excl;
    }
}

__global__ void k_fill(const int* __restrict__ ei, int E) {
    int e = blockIdx.x * blockDim.x + threadIdx.x;
    if (e >= E) return;
    int u = ei[2 * e];
    int it = ei[2 * e + 1] + NU;
    float du = g_dinv[u];
    float di = g_dinv[it];
    int p1 = atomicAdd(&g_cursor[it], 1);   // dst = item, src = user
    g_edges[p1] = make_int2(u, __float_as_int(du));
    int p2 = atomicAdd(&g_cursor[u], 1);    // dst = user, src = item
    g_edges[p2] = make_int2(it, __float_as_int(di));
}

// ---------------- init combined X / ACC (user parts + item g part) ----------
__global__ void k_initX(const float* __restrict__ ue, const float* __restrict__ uev,
                        const float* __restrict__ uet, const float* __restrict__ ie) {
    int i = blockIdx.x * blockDim.x + threadIdx.x;     // over NU*64
    if (i >= NU * 64) return;
    int u = i >> 6;
    int c = i & 63;
    size_t ub = (size_t)u * FW;
    float a = ue[i], b = uev[i], d = uet[i], e = ie[i];
    g_X[ub + c] = a;        g_ACC[ub + c] = a;
    g_X[ub + 64 + c] = b;   g_ACC[ub + 64 + c] = b;
    g_X[ub + 128 + c] = d;  g_ACC[ub + 128 + c] = d;
    size_t ib = (size_t)(NU + u) * FW;
    g_X[ib + c] = e;        g_ACC[ib + c] = e;
}

// ---------------- SGEMM: C(MxN=64) = A(MxK) @ W(64xK)^T [+ bias] ------------
// mode 0: v-projection  -> X/ACC item rows, col offset 64, ld=FW, +bias
// mode 1: t-projection  -> X/ACC item rows, col offset 128, ld=FW, +bias
// mode 2: dense layer   -> A = g_X viewed (3N x 64), out = g_H, ld=64, no bias
__global__ void __launch_bounds__(128) k_sgemm(const float* __restrict__ Ain, int M, int K,
                                               const float* __restrict__ W,
                                               const float* __restrict__ bias, int mode) {
    const float* A = (mode == 2) ? g_X : Ain;
    float* out1;
    float* out2;
    int ld;
    if (mode == 2) {
        out1 = g_H; out2 = nullptr; ld = 64;
    } else {
        size_t off = (size_t)NU * FW + ((mode == 0) ? 64 : 128);
        out1 = g_X + off; out2 = g_ACC + off; ld = FW;
    }

    __shared__ float As[32][132];   // [k][row], pad keeps 16B alignment, conflict-light
    __shared__ float Bs[32][68];    // [k][col]

    int tid = threadIdx.x;
    int rowBase = blockIdx.x * 128;
    float acc[8][8];
#pragma unroll
    for (int i = 0; i < 8; ++i)
#pragma unroll
        for (int j = 0; j < 8; ++j) acc[i][j] = 0.f;

    int tr = (tid >> 3) * 8;  // row frag base 0..120
    int tc = (tid & 7) * 8;   // col frag base 0..56

    for (int k0 = 0; k0 < K; k0 += 32) {
        // A tile: 128 rows x 32 k, coalesced float4
#pragma unroll
        for (int it = 0; it < 8; ++it) {
            int r = it * 16 + (tid >> 3);
            int kq = (tid & 7) * 4;
            float4 v = make_float4(0.f, 0.f, 0.f, 0.f);
            int gr = rowBase + r;
            if (gr < M) v = *(const float4*)(A + (size_t)gr * K + k0 + kq);
            As[kq + 0][r] = v.x;
            As[kq + 1][r] = v.y;
            As[kq + 2][r] = v.z;
            As[kq + 3][r] = v.w;
        }
        // B tile: W is 64 x K row-major; store transposed -> Bs[k][c]
#pragma unroll
        for (int it = 0; it < 4; ++it) {
            int c = tid >> 1;
            int k = (tid & 1) * 16 + it * 4;
            float4 v = *(const float4*)(W + (size_t)c * K + k0 + k);
            Bs[k + 0][c] = v.x;
            Bs[k + 1][c] = v.y;
            Bs[k + 2][c] = v.z;
            Bs[k + 3][c] = v.w;
        }
        __syncthreads();
#pragma unroll 8
        for (int kk = 0; kk < 32; ++kk) {
            float a[8], b[8];
#pragma unroll
            for (int i = 0; i < 8; ++i) a[i] = As[kk][tr + i];
#pragma unroll
            for (int i = 0; i < 8; ++i) b[i] = Bs[kk][tc + i];
#pragma unroll
            for (int i = 0; i < 8; ++i)
#pragma unroll
                for (int j = 0; j < 8; ++j) acc[i][j] = fmaf(a[i], b[j], acc[i][j]);
        }
        __syncthreads();
    }

#pragma unroll
    for (int i = 0; i < 8; ++i) {
        int r = rowBase + tr + i;
        if (r < M) {
#pragma unroll
            for (int j = 0; j < 8; ++j) {
                int c = tc + j;
                float v = acc[i][j];
                if (mode != 2) v += __ldg(&bias[c]);
                size_t o = (size_t)r * ld + c;
                out1[o] = v;
                if (mode != 2) out2[o] = v;
            }
        }
    }
}

// ---------------- aggregation: X = dinv[dst]*(sum w*H[src] + dinv[dst]*H[dst]) + b;
//                  ACC += X.  Warp per node, 6 float2 lanes cover 192 cols. --
#define AGG_STEP(e)                                                     \
    {                                                                   \
        int s_ = (e).x;                                                 \
        float w_ = __int_as_float((e).y);                               \
        size_t sb_ = (size_t)s_ * FW2 + lane;                           \
        float2 v0_ = __ldg(&H2[sb_]);                                   \
        float2 v1_ = __ldg(&H2[sb_ + 32]);                              \
        float2 v2_ = __ldg(&H2[sb_ + 64]);                              \
        a0x += w_ * v0_.x; a0y += w_ * v0_.y;                           \
        a1x += w_ * v1_.x; a1y += w_ * v1_.y;                           \
        a2x += w_ * v2_.x; a2y += w_ * v2_.y;                           \
    }

__global__ void __launch_bounds__(256) k_agg(const float* __restrict__ bias) {
    int warp = threadIdx.x >> 5;
    int lane = threadIdx.x & 31;
    int node = blockIdx.x * 8 + warp;
    if (node >= NN) return;

    const float2* H2 = (const float2*)g_H;
    float2* X2 = (float2*)g_X;
    float2* A2 = (float2*)g_ACC;

    float dn = g_dinv[node];
    size_t base = (size_t)node * FW2 + lane;

    // self-loop contribution (weight dinv[node]; outer dinv applied at end -> dinv^2)
    float2 h0 = __ldg(&H2[base]);
    float2 h1 = __ldg(&H2[base + 32]);
    float2 h2 = __ldg(&H2[base + 64]);
    float a0x = dn * h0.x, a0y = dn * h0.y;
    float a1x = dn * h1.x, a1y = dn * h1.y;
    float a2x = dn * h2.x, a2y = dn * h2.y;

    int p = g_rowptr[node];
    int cnt = g_deg[node] - 1;

    int j = 0;
    for (; j + 4 <= cnt; j += 4) {
        int2 e0 = __ldg(&g_edges[p + j]);
        int2 e1 = __ldg(&g_edges[p + j + 1]);
        int2 e2 = __ldg(&g_edges[p + j + 2]);
        int2 e3 = __ldg(&g_edges[p + j + 3]);
        AGG_STEP(e0); AGG_STEP(e1); AGG_STEP(e2); AGG_STEP(e3);
    }
    for (; j < cnt; ++j) {
        int2 e = __ldg(&g_edges[p + j]);
        AGG_STEP(e);
    }

    float bx = __ldg(&bias[2 * lane]);
    float by = __ldg(&bias[2 * lane + 1]);
    float2 o0 = make_float2(a0x * dn + bx, a0y * dn + by);
    float2 o1 = make_float2(a1x * dn + bx, a1y * dn + by);
    float2 o2 = make_float2(a2x * dn + bx, a2y * dn + by);
    X2[base] = o0; X2[base + 32] = o1; X2[base + 64] = o2;
    float2 c0 = A2[base];      c0.x += o0.x; c0.y += o0.y; A2[base] = c0;
    float2 c1 = A2[base + 32]; c1.x += o1.x; c1.y += o1.y; A2[base + 32] = c1;
    float2 c2 = A2[base + 64]; c2.x += o2.x; c2.y += o2.y; A2[base + 64] = c2;
}

// ---------------- output assembly: 6 sections, ACC/3 -------------------------
__global__ void k_out(float* __restrict__ out) {
    int i = blockIdx.x * blockDim.x + threadIdx.x;
    if (i >= 6 * NU * 64) return;
    int sec = i / (NU * 64);
    int rem = i - sec * (NU * 64);
    int r = rem >> 6;
    int c = rem & 63;
    int stack = sec >> 1;
    int item = sec & 1;
    int node = r + (item ? NU : 0);
    out[i] = g_ACC[(size_t)node * FW + stack * 64 + c] * (1.f / 3.f);
}

// ---------------- launch ------------------------------------------------------
extern "C" void kernel_launch(void* const* d_in, const int* in_sizes, int n_in,
                              void* d_out, int out_size) {
    const int* ei = (const int*)d_in[0];
    const float* v_feat = (const float*)d_in[1];
    const float* t_feat = (const float*)d_in[2];
    const float* user_emb = (const float*)d_in[3];
    const float* item_emb = (const float*)d_in[4];
    const float* user_emb_v = (const float*)d_in[5];
    const float* user_emb_t = (const float*)d_in[6];
    const float* W_v = (const float*)d_in[7];
    const float* b_v = (const float*)d_in[8];
    const float* W_t = (const float*)d_in[9];
    const float* b_t = (const float*)d_in[10];
    const float* W0 = (const float*)d_in[11];
    const float* b0 = (const float*)d_in[12];
    const float* W1 = (const float*)d_in[13];
    const float* b1 = (const float*)d_in[14];
    float* out = (float*)d_out;

    int E = in_sizes[0] / 2;
    if (E > EMAX) E = EMAX;

    // graph build
    k_deg_init<<<(NN + 255) / 256, 256>>>();
    k_count<<<(E + 255) / 256, 256>>>(ei, E);
    k_dinv<<<(NN + 255) / 256, 256>>>();
    k_scan1<<<NB_SCAN, 512>>>();
    k_scan2<<<1, 1>>>();
    k_scan3<<<NB_SCAN, 512>>>();
    k_fill<<<(E + 255) / 256, 256>>>(ei, E);

    // initial embeddings
    k_initX<<<(NU * 64 + 255) / 256, 256>>>(user_emb, user_emb_v, user_emb_t, item_emb);
    k_sgemm<<<(NU + 127) / 128, 128>>>(v_feat, NU, 2048, W_v, b_v, 0);
    k_sgemm<<<(NU + 127) / 128, 128>>>(t_feat, NU, 768, W_t, b_t, 1);

    // layer 0
    k_sgemm<<<(3 * NN + 127) / 128, 128>>>(nullptr, 3 * NN, 64, W0, nullptr, 2);
    k_agg<<<(NN + 7) / 8, 256>>>(b0);
    // layer 1
    k_sgemm<<<(3 * NN + 127) / 128, 128>>>(nullptr, 3 * NN, 64, W1, nullptr, 2);
    k_agg<<<(NN + 7) / 8, 256>>>(b1);

    k_out<<<(6 * NU * 64 + 255) / 256, 256>>>(out);
}

// round 6
// speedup vs baseline: 1.1846x; 1.1846x over previous
#include <cuda_runtime.h>
#include <cuda_fp16.h>

#define NU 50000
#define NI 50000
#define NN 100000
#define DIM 64
#define EMAX 2000000
#define FW 192              // combined feature width: 3 stacks x 64
#define FW2 96              // in float2 / half2 units
#define NB_SCAN 196         // 196*512 >= 100000

// ---------------- device scratch (static; no dynamic allocation) -------------
__device__ int     g_deg[NN];
__device__ float   g_dinv[NN];
__device__ int     g_rowptr[NN];
__device__ int     g_cursor[NN];
__device__ int2    g_edges[2 * EMAX];          // (src, bitcast(dinv[src]))
__device__ float   g_X[(size_t)NN * FW];       // current layer input (fp32, 76.8 MB)
__device__ __half2 g_Hh[(size_t)NN * FW2];     // x @ W.T in fp16     (38.4 MB, L2-resident)
__device__ float   g_ACC[(size_t)NN * FW];     // running sum         (76.8 MB)
__device__ int     g_partial[NB_SCAN];

// ---------------- graph build ------------------------------------------------
__global__ void k_deg_init() {
    int n = blockIdx.x * blockDim.x + threadIdx.x;
    if (n < NN) g_deg[n] = 1;                 // self loop
}

__global__ void k_count(const int* __restrict__ ei, int E) {
    int e = blockIdx.x * blockDim.x + threadIdx.x;
    if (e >= E) return;
    int u = ei[2 * e];
    int it = ei[2 * e + 1] + NU;
    atomicAdd(&g_deg[u], 1);
    atomicAdd(&g_deg[it], 1);
}

__global__ void k_dinv() {
    int n = blockIdx.x * blockDim.x + threadIdx.x;
    if (n < NN) g_dinv[n] = rsqrtf((float)g_deg[n]);
}

__global__ void k_scan1() {
    __shared__ int sh[512];
    int t = threadIdx.x;
    int idx = blockIdx.x * 512 + t;
    int v = (idx < NN) ? (g_deg[idx] - 1) : 0;
    sh[t] = v;
    __syncthreads();
    for (int off = 256; off > 0; off >>= 1) {
        if (t < off) sh[t] += sh[t + off];
        __syncthreads();
    }
    if (t == 0) g_partial[blockIdx.x] = sh[0];
}

__global__ void k_scan2() {
    int run = 0;
    for (int b = 0; b < NB_SCAN; ++b) {
        int v = g_partial[b];
        g_partial[b] = run;
        run += v;
    }
}

__global__ void k_scan3() {
    __shared__ int sh[512];
    int t = threadIdx.x;
    int idx = blockIdx.x * 512 + t;
    int v = (idx < NN) ? (g_deg[idx] - 1) : 0;
    sh[t] = v;
    __syncthreads();
    for (int off = 1; off < 512; off <<= 1) {
        int x = (t >= off) ? sh[t - off] : 0;
        __syncthreads();
        sh[t] += x;
        __syncthreads();
    }
    if (idx < NN) {
        int excl = g_partial[blockIdx.x] + sh[t] - v;
        g_rowptr[idx] = excl;
        g_cursor[idx] = excl;
    }
}

__global__ void k_fill(const int* __restrict__ ei, int E) {
    int e = blockIdx.x * blockDim.x + threadIdx.x;
    if (e >= E) return;
    int u = ei[2 * e];
    int it = ei[2 * e + 1] + NU;
    float du = g_dinv[u];
    float di = g_dinv[it];
    int p1 = atomicAdd(&g_cursor[it], 1);   // dst = item, src = user
    g_edges[p1] = make_int2(u, __float_as_int(du));
    int p2 = atomicAdd(&g_cursor[u], 1);    // dst = user, src = item
    g_edges[p2] = make_int2(it, __float_as_int(di));
}

// ---------------- init combined X / ACC -------------------------------------
__global__ void k_initX(const float* __restrict__ ue, const float* __restrict__ uev,
                        const float* __restrict__ uet, const float* __restrict__ ie) {
    int i = blockIdx.x * blockDim.x + threadIdx.x;     // over NU*64
    if (i >= NU * 64) return;
    int u = i >> 6;
    int c = i & 63;
    size_t ub = (size_t)u * FW;
    float a = ue[i], b = uev[i], d = uet[i], e = ie[i];
    g_X[ub + c] = a;        g_ACC[ub + c] = a;
    g_X[ub + 64 + c] = b;   g_ACC[ub + 64 + c] = b;
    g_X[ub + 128 + c] = d;  g_ACC[ub + 128 + c] = d;
    size_t ib = (size_t)(NU + u) * FW;
    g_X[ib + c] = e;        g_ACC[ib + c] = e;
}

// ---------------- SGEMM: C(Mx64) = A(MxK) @ W(64xK)^T [+ bias] --------------
// mode 0: v-projection  -> X/ACC item rows, col offset 64, ld=FW, +bias (fp32 out)
// mode 1: t-projection  -> X/ACC item rows, col offset 128, ld=FW, +bias (fp32 out)
// mode 2: dense layer   -> A = g_X viewed (3N x 64), out = g_Hh (fp16), no bias
__global__ void __launch_bounds__(128) k_sgemm(const float* __restrict__ Ain, int M, int K,
                                               const float* __restrict__ W,
                                               const float* __restrict__ bias, int mode) {
    const float* A = (mode == 2) ? g_X : Ain;
    float* out1 = nullptr;
    float* out2 = nullptr;
    if (mode != 2) {
        size_t off = (size_t)NU * FW + ((mode == 0) ? 64 : 128);
        out1 = g_X + off; out2 = g_ACC + off;
    }

    __shared__ float As[32][132];
    __shared__ float Bs[32][68];

    int tid = threadIdx.x;
    int rowBase = blockIdx.x * 128;
    float acc[8][8];
#pragma unroll
    for (int i = 0; i < 8; ++i)
#pragma unroll
        for (int j = 0; j < 8; ++j) acc[i][j] = 0.f;

    int tr = (tid >> 3) * 8;  // row frag base 0..120
    int tc = (tid & 7) * 8;   // col frag base 0..56

    for (int k0 = 0; k0 < K; k0 += 32) {
#pragma unroll
        for (int it = 0; it < 8; ++it) {
            int r = it * 16 + (tid >> 3);
            int kq = (tid & 7) * 4;
            float4 v = make_float4(0.f, 0.f, 0.f, 0.f);
            int gr = rowBase + r;
            if (gr < M) v = *(const float4*)(A + (size_t)gr * K + k0 + kq);
            As[kq + 0][r] = v.x;
            As[kq + 1][r] = v.y;
            As[kq + 2][r] = v.z;
            As[kq + 3][r] = v.w;
        }
#pragma unroll
        for (int it = 0; it < 4; ++it) {
            int c = tid >> 1;
            int k = (tid & 1) * 16 + it * 4;
            float4 v = *(const float4*)(W + (size_t)c * K + k0 + k);
            Bs[k + 0][c] = v.x;
            Bs[k + 1][c] = v.y;
            Bs[k + 2][c] = v.z;
            Bs[k + 3][c] = v.w;
        }
        __syncthreads();
#pragma unroll 8
        for (int kk = 0; kk < 32; ++kk) {
            float a[8], b[8];
#pragma unroll
            for (int i = 0; i < 8; ++i) a[i] = As[kk][tr + i];
#pragma unroll
            for (int i = 0; i < 8; ++i) b[i] = Bs[kk][tc + i];
#pragma unroll
            for (int i = 0; i < 8; ++i)
#pragma unroll
                for (int j = 0; j < 8; ++j) acc[i][j] = fmaf(a[i], b[j], acc[i][j]);
        }
        __syncthreads();
    }

    if (mode == 2) {
#pragma unroll
        for (int i = 0; i < 8; ++i) {
            int r = rowBase + tr + i;
            if (r < M) {
#pragma unroll
                for (int j = 0; j < 8; j += 2) {
                    g_Hh[(size_t)r * 32 + ((tc + j) >> 1)] =
                        __floats2half2_rn(acc[i][j], acc[i][j + 1]);
                }
            }
        }
    } else {
#pragma unroll
        for (int i = 0; i < 8; ++i) {
            int r = rowBase + tr + i;
            if (r < M) {
#pragma unroll
                for (int j = 0; j < 8; ++j) {
                    int c = tc + j;
                    float v = acc[i][j] + __ldg(&bias[c]);
                    size_t o = (size_t)r * FW + c;
                    out1[o] = v;
                    out2[o] = v;
                }
            }
        }
    }
}

// ---------------- aggregation over fp16 H ------------------------------------
// x_new = dinv[dst]*(sum w*H[src] + dinv[dst]*H[dst]) + b
// FINAL=0: X = x_new; ACC += x_new
// FINAL=1: out[section] = (ACC + x_new)/3   (no X/ACC stores)
#define AGG_STEP(e)                                                     \
    {                                                                   \
        int s_ = (e).x;                                                 \
        float w_ = __int_as_float((e).y);                               \
        size_t sb_ = (size_t)s_ * FW2 + lane;                           \
        float2 v0_ = __half22float2(__ldg(&g_Hh[sb_]));                 \
        float2 v1_ = __half22float2(__ldg(&g_Hh[sb_ + 32]));            \
        float2 v2_ = __half22float2(__ldg(&g_Hh[sb_ + 64]));            \
        a0x += w_ * v0_.x; a0y += w_ * v0_.y;                           \
        a1x += w_ * v1_.x; a1y += w_ * v1_.y;                           \
        a2x += w_ * v2_.x; a2y += w_ * v2_.y;                           \
    }

template <int FINAL>
__global__ void __launch_bounds__(256) k_agg(const float* __restrict__ bias,
                                             float* __restrict__ out) {
    int warp = threadIdx.x >> 5;
    int lane = threadIdx.x & 31;
    int node = blockIdx.x * 8 + warp;
    if (node >= NN) return;

    float2* X2 = (float2*)g_X;
    float2* A2 = (float2*)g_ACC;

    float dn = g_dinv[node];
    size_t base = (size_t)node * FW2 + lane;

    // self-loop (weight dinv; outer dinv at end -> dinv^2)
    float2 h0 = __half22float2(__ldg(&g_Hh[base]));
    float2 h1 = __half22float2(__ldg(&g_Hh[base + 32]));
    float2 h2 = __half22float2(__ldg(&g_Hh[base + 64]));
    float a0x = dn * h0.x, a0y = dn * h0.y;
    float a1x = dn * h1.x, a1y = dn * h1.y;
    float a2x = dn * h2.x, a2y = dn * h2.y;

    int p = g_rowptr[node];
    int cnt = g_deg[node] - 1;

    int j = 0;
    for (; j + 4 <= cnt; j += 4) {
        int2 e0 = __ldg(&g_edges[p + j]);
        int2 e1 = __ldg(&g_edges[p + j + 1]);
        int2 e2 = __ldg(&g_edges[p + j + 2]);
        int2 e3 = __ldg(&g_edges[p + j + 3]);
        AGG_STEP(e0); AGG_STEP(e1); AGG_STEP(e2); AGG_STEP(e3);
    }
    for (; j < cnt; ++j) {
        int2 e = __ldg(&g_edges[p + j]);
        AGG_STEP(e);
    }

    float bx = __ldg(&bias[2 * lane]);
    float by = __ldg(&bias[2 * lane + 1]);
    float2 o0 = make_float2(a0x * dn + bx, a0y * dn + by);
    float2 o1 = make_float2(a1x * dn + bx, a1y * dn + by);
    float2 o2 = make_float2(a2x * dn + bx, a2y * dn + by);

    if (FINAL) {
        const float inv3 = 1.f / 3.f;
        int itm = (node >= NU) ? 1 : 0;
        int r = node - itm * NU;
        float2* O2 = (float2*)out;
        float2 c0 = A2[base], c1 = A2[base + 32], c2 = A2[base + 64];
        float2 r0 = make_float2((c0.x + o0.x) * inv3, (c0.y + o0.y) * inv3);
        float2 r1 = make_float2((c1.x + o1.x) * inv3, (c1.y + o1.y) * inv3);
        float2 r2 = make_float2((c2.x + o2.x) * inv3, (c2.y + o2.y) * inv3);
        // section = 2*stack + itm ; each section NU*64 floats = NU*32 float2
        O2[(size_t)(0 + itm) * (NU * 32) + (size_t)r * 32 + lane] = r0;
        O2[(size_t)(2 + itm) * (NU * 32) + (size_t)r * 32 + lane] = r1;
        O2[(size_t)(4 + itm) * (NU * 32) + (size_t)r * 32 + lane] = r2;
    } else {
        X2[base] = o0; X2[base + 32] = o1; X2[base + 64] = o2;
        float2 c0 = A2[base];      c0.x += o0.x; c0.y += o0.y; A2[base] = c0;
        float2 c1 = A2[base + 32]; c1.x += o1.x; c1.y += o1.y; A2[base + 32] = c1;
        float2 c2 = A2[base + 64]; c2.x += o2.x; c2.y += o2.y; A2[base + 64] = c2;
    }
}

// ---------------- launch ------------------------------------------------------
extern "C" void kernel_launch(void* const* d_in, const int* in_sizes, int n_in,
                              void* d_out, int out_size) {
    const int* ei = (const int*)d_in[0];
    const float* v_feat = (const float*)d_in[1];
    const float* t_feat = (const float*)d_in[2];
    const float* user_emb = (const float*)d_in[3];
    const float* item_emb = (const float*)d_in[4];
    const float* user_emb_v = (const float*)d_in[5];
    const float* user_emb_t = (const float*)d_in[6];
    const float* W_v = (const float*)d_in[7];
    const float* b_v = (const float*)d_in[8];
    const float* W_t = (const float*)d_in[9];
    const float* b_t = (const float*)d_in[10];
    const float* W0 = (const float*)d_in[11];
    const float* b0 = (const float*)d_in[12];
    const float* W1 = (const float*)d_in[13];
    const float* b1 = (const float*)d_in[14];
    float* out = (float*)d_out;

    int E = in_sizes[0] / 2;
    if (E > EMAX) E = EMAX;

    // graph build
    k_deg_init<<<(NN + 255) / 256, 256>>>();
    k_count<<<(E + 255) / 256, 256>>>(ei, E);
    k_dinv<<<(NN + 255) / 256, 256>>>();
    k_scan1<<<NB_SCAN, 512>>>();
    k_scan2<<<1, 1>>>();
    k_scan3<<<NB_SCAN, 512>>>();
    k_fill<<<(E + 255) / 256, 256>>>(ei, E);

    // initial embeddings
    k_initX<<<(NU * 64 + 255) / 256, 256>>>(user_emb, user_emb_v, user_emb_t, item_emb);
    k_sgemm<<<(NU + 127) / 128, 128>>>(v_feat, NU, 2048, W_v, b_v, 0);
    k_sgemm<<<(NU + 127) / 128, 128>>>(t_feat, NU, 768, W_t, b_t, 1);

    // layer 0
    k_sgemm<<<(3 * NN + 127) / 128, 128>>>(nullptr, 3 * NN, 64, W0, nullptr, 2);
    k_agg<0><<<(NN + 7) / 8, 256>>>(b0, nullptr);
    // layer 1 (fused output)
    k_sgemm<<<(3 * NN + 127) / 128, 128>>>(nullptr, 3 * NN, 64, W1, nullptr, 2);
    k_agg<1><<<(NN + 7) / 8, 256>>>(b1, out);
}

// round 7
// speedup vs baseline: 1.8357x; 1.5496x over previous
#include <cuda_runtime.h>
#include <cuda_fp16.h>
#include <mma.h>
using namespace nvcuda;

#define NU 50000
#define NI 50000
#define NN 100000
#define DIM 64
#define EMAX 2000000
#define FW 192              // combined feature width: 3 stacks x 64
#define FW2 96              // in float2 / half2 units
#define NB_SCAN 196         // 196*512 >= 100000

// ---------------- device scratch (static; no dynamic allocation) -------------
__device__ int     g_deg[NN];
__device__ float   g_dinv[NN];
__device__ int     g_rowptr[NN];
__device__ int     g_cursor[NN];
__device__ int2    g_edges[2 * EMAX];          // (src, bitcast(dinv[src]))
__device__ float   g_X[(size_t)NN * FW];       // current layer input (fp32, 76.8 MB)
__device__ __half2 g_Hh[(size_t)NN * FW2];     // x @ W.T in fp16     (38.4 MB, L2-resident)
__device__ float   g_ACC[(size_t)NN * FW];     // running sum         (76.8 MB)
__device__ int     g_partial[NB_SCAN];

// ---------------- graph build ------------------------------------------------
__global__ void k_deg_init() {
    int n = blockIdx.x * blockDim.x + threadIdx.x;
    if (n < NN) g_deg[n] = 1;                 // self loop
}

__global__ void k_count(const int* __restrict__ ei, int E) {
    int e = blockIdx.x * blockDim.x + threadIdx.x;
    if (e >= E) return;
    int u = ei[2 * e];
    int it = ei[2 * e + 1] + NU;
    atomicAdd(&g_deg[u], 1);
    atomicAdd(&g_deg[it], 1);
}

__global__ void k_dinv() {
    int n = blockIdx.x * blockDim.x + threadIdx.x;
    if (n < NN) g_dinv[n] = rsqrtf((float)g_deg[n]);
}

__global__ void k_scan1() {
    __shared__ int sh[512];
    int t = threadIdx.x;
    int idx = blockIdx.x * 512 + t;
    int v = (idx < NN) ? (g_deg[idx] - 1) : 0;
    sh[t] = v;
    __syncthreads();
    for (int off = 256; off > 0; off >>= 1) {
        if (t < off) sh[t] += sh[t + off];
        __syncthreads();
    }
    if (t == 0) g_partial[blockIdx.x] = sh[0];
}

__global__ void k_scan2() {
    int run = 0;
    for (int b = 0; b < NB_SCAN; ++b) {
        int v = g_partial[b];
        g_partial[b] = run;
        run += v;
    }
}

__global__ void k_scan3() {
    __shared__ int sh[512];
    int t = threadIdx.x;
    int idx = blockIdx.x * 512 + t;
    int v = (idx < NN) ? (g_deg[idx] - 1) : 0;
    sh[t] = v;
    __syncthreads();
    for (int off = 1; off < 512; off <<= 1) {
        int x = (t >= off) ? sh[t - off] : 0;
        __syncthreads();
        sh[t] += x;
        __syncthreads();
    }
    if (idx < NN) {
        int excl = g_partial[blockIdx.x] + sh[t] - v;
        g_rowptr[idx] = excl;
        g_cursor[idx] = excl;
    }
}

__global__ void k_fill(const int* __restrict__ ei, int E) {
    int e = blockIdx.x * blockDim.x + threadIdx.x;
    if (e >= E) return;
    int u = ei[2 * e];
    int it = ei[2 * e + 1] + NU;
    float du = g_dinv[u];
    float di = g_dinv[it];
    int p1 = atomicAdd(&g_cursor[it], 1);   // dst = item, src = user
    g_edges[p1] = make_int2(u, __float_as_int(du));
    int p2 = atomicAdd(&g_cursor[u], 1);    // dst = user, src = item
    g_edges[p2] = make_int2(it, __float_as_int(di));
}

// ---------------- init combined X / ACC -------------------------------------
__global__ void k_initX(const float* __restrict__ ue, const float* __restrict__ uev,
                        const float* __restrict__ uet, const float* __restrict__ ie) {
    int i = blockIdx.x * blockDim.x + threadIdx.x;     // over NU*64
    if (i >= NU * 64) return;
    int u = i >> 6;
    int c = i & 63;
    size_t ub = (size_t)u * FW;
    float a = ue[i], b = uev[i], d = uet[i], e = ie[i];
    g_X[ub + c] = a;        g_ACC[ub + c] = a;
    g_X[ub + 64 + c] = b;   g_ACC[ub + 64 + c] = b;
    g_X[ub + 128 + c] = d;  g_ACC[ub + 128 + c] = d;
    size_t ib = (size_t)(NU + u) * FW;
    g_X[ib + c] = e;        g_ACC[ib + c] = e;
}

// ---------------- tensor-core GEMM: C(Mx64) = A(MxK) @ W(64xK)^T ------------
// fp32 inputs converted to fp16 in smem; fp32 accumulate (HMMA).
// OUT_MODE 0: +bias -> X/ACC item rows col offset 64  (fp32)
// OUT_MODE 1: +bias -> X/ACC item rows col offset 128 (fp32)
// OUT_MODE 2: no bias -> g_Hh (fp16), A = g_X viewed (3N x 64)
// Block: 256 thr (8 warps). Tile: 128(M) x 64(N), K-chunk 32.
#define LDA 40   // padded smem ld (halves)
#define LDC 72   // padded smem ld (floats)

template <int OUT_MODE>
__global__ void __launch_bounds__(256) k_wgemm(const float* __restrict__ Ain, int M, int K,
                                               const float* __restrict__ W,
                                               const float* __restrict__ bias) {
    const float* A = (OUT_MODE == 2) ? g_X : Ain;

    __shared__ __align__(16) char raw[128 * LDC * 4];   // 36864 B
    half*  As = (half*)raw;                  // [128][LDA]
    half*  Ws = (half*)(raw + 128 * LDA * 2);// [64][LDA]
    float* Cs = (float*)raw;                 // [128][LDC] (reused after K loop)

    int tid = threadIdx.x;
    int warp = tid >> 5;
    int rowBase = blockIdx.x * 128;

    wmma::fragment<wmma::accumulator, 16, 16, 16, float> acc[4];
#pragma unroll
    for (int nf = 0; nf < 4; ++nf) wmma::fill_fragment(acc[nf], 0.f);

    int lr = tid >> 1;               // 0..127  (A tile row)
    int lk = (tid & 1) * 16;         // 0 or 16 (A tile k base)
    bool rowOK = (rowBase + lr) < M;
    const float* Arow = A + (size_t)(rowBase + lr) * K + lk;

    for (int k0 = 0; k0 < K; k0 += 32) {
        // A tile: 128 x 32 fp32 -> fp16
#pragma unroll
        for (int q = 0; q < 4; ++q) {
            float4 v = make_float4(0.f, 0.f, 0.f, 0.f);
            if (rowOK) v = *(const float4*)(Arow + k0 + q * 4);
            half* dst = As + lr * LDA + lk + q * 4;
            *(half2*)(dst)     = __floats2half2_rn(v.x, v.y);
            *(half2*)(dst + 2) = __floats2half2_rn(v.z, v.w);
        }
        // W tile: 64 x 32 fp32 -> fp16  (2 float4 per thread)
#pragma unroll
        for (int it = 0; it < 2; ++it) {
            int f = tid + it * 256;          // float4 idx 0..511
            int c = f >> 3;
            int kq = (f & 7) * 4;
            float4 v = *(const float4*)(W + (size_t)c * K + k0 + kq);
            half* dst = Ws + c * LDA + kq;
            *(half2*)(dst)     = __floats2half2_rn(v.x, v.y);
            *(half2*)(dst + 2) = __floats2half2_rn(v.z, v.w);
        }
        __syncthreads();

#pragma unroll
        for (int kk = 0; kk < 32; kk += 16) {
            wmma::fragment<wmma::matrix_a, 16, 16, 16, half, wmma::row_major> af;
            wmma::load_matrix_sync(af, As + (warp * 16) * LDA + kk, LDA);
#pragma unroll
            for (int nf = 0; nf < 4; ++nf) {
                wmma::fragment<wmma::matrix_b, 16, 16, 16, half, wmma::col_major> bf;
                wmma::load_matrix_sync(bf, Ws + (nf * 16) * LDA + kk, LDA);
                wmma::mma_sync(acc[nf], af, bf, acc[nf]);
            }
        }
        __syncthreads();
    }

    // stage C through smem
#pragma unroll
    for (int nf = 0; nf < 4; ++nf)
        wmma::store_matrix_sync(Cs + (warp * 16) * LDC + nf * 16, acc[nf], LDC, wmma::mem_row_major);
    __syncthreads();

    // epilogue: 2 threads per row, 32 cols each
    int r = tid >> 1;
    int h = (tid & 1) * 32;
    int gr = rowBase + r;
    if (gr < M) {
        const float* src = Cs + r * LDC + h;
        if (OUT_MODE == 2) {
            __half2* Hrow = g_Hh + (size_t)gr * 32 + (h >> 1);
#pragma unroll
            for (int q = 0; q < 16; ++q)
                Hrow[q] = __floats2half2_rn(src[2 * q], src[2 * q + 1]);
        } else {
            size_t off = (size_t)NU * FW + ((OUT_MODE == 0) ? 64 : 128);
            float* o1 = g_X + off + (size_t)gr * FW + h;
            float* o2 = g_ACC + off + (size_t)gr * FW + h;
#pragma unroll
            for (int q = 0; q < 8; ++q) {
                float4 v = *(const float4*)(src + q * 4);
                v.x += __ldg(&bias[h + q * 4]);
                v.y += __ldg(&bias[h + q * 4 + 1]);
                v.z += __ldg(&bias[h + q * 4 + 2]);
                v.w += __ldg(&bias[h + q * 4 + 3]);
                *(float4*)(o1 + q * 4) = v;
                *(float4*)(o2 + q * 4) = v;
            }
        }
    }
}

// ---------------- aggregation over fp16 H ------------------------------------
// x_new = dinv[dst]*(sum w*H[src] + dinv[dst]*H[dst]) + b
// FINAL=0: X = x_new; ACC += x_new
// FINAL=1: out[section] = (ACC + x_new)/3
#define AGG_STEP(e)                                                     \
    {                                                                   \
        int s_ = (e).x;                                                 \
        float w_ = __int_as_float((e).y);                               \
        size_t sb_ = (size_t)s_ * FW2 + lane;                           \
        float2 v0_ = __half22float2(__ldg(&g_Hh[sb_]));                 \
        float2 v1_ = __half22float2(__ldg(&g_Hh[sb_ + 32]));            \
        float2 v2_ = __half22float2(__ldg(&g_Hh[sb_ + 64]));            \
        a0x += w_ * v0_.x; a0y += w_ * v0_.y;                           \
        a1x += w_ * v1_.x; a1y += w_ * v1_.y;                           \
        a2x += w_ * v2_.x; a2y += w_ * v2_.y;                           \
    }

template <int FINAL>
__global__ void __launch_bounds__(256) k_agg(const float* __restrict__ bias,
                                             float* __restrict__ out) {
    int warp = threadIdx.x >> 5;
    int lane = threadIdx.x & 31;
    int node = blockIdx.x * 8 + warp;
    if (node >= NN) return;

    float2* X2 = (float2*)g_X;
    float2* A2 = (float2*)g_ACC;

    float dn = g_dinv[node];
    size_t base = (size_t)node * FW2 + lane;

    float2 h0 = __half22float2(__ldg(&g_Hh[base]));
    float2 h1 = __half22float2(__ldg(&g_Hh[base + 32]));
    float2 h2 = __half22float2(__ldg(&g_Hh[base + 64]));
    float a0x = dn * h0.x, a0y = dn * h0.y;
    float a1x = dn * h1.x, a1y = dn * h1.y;
    float a2x = dn * h2.x, a2y = dn * h2.y;

    int p = g_rowptr[node];
    int cnt = g_deg[node] - 1;

    int j = 0;
    for (; j + 4 <= cnt; j += 4) {
        int2 e0 = __ldg(&g_edges[p + j]);
        int2 e1 = __ldg(&g_edges[p + j + 1]);
        int2 e2 = __ldg(&g_edges[p + j + 2]);
        int2 e3 = __ldg(&g_edges[p + j + 3]);
        AGG_STEP(e0); AGG_STEP(e1); AGG_STEP(e2); AGG_STEP(e3);
    }
    for (; j < cnt; ++j) {
        int2 e = __ldg(&g_edges[p + j]);
        AGG_STEP(e);
    }

    float bx = __ldg(&bias[2 * lane]);
    float by = __ldg(&bias[2 * lane + 1]);
    float2 o0 = make_float2(a0x * dn + bx, a0y * dn + by);
    float2 o1 = make_float2(a1x * dn + bx, a1y * dn + by);
    float2 o2 = make_float2(a2x * dn + bx, a2y * dn + by);

    if (FINAL) {
        const float inv3 = 1.f / 3.f;
        int itm = (node >= NU) ? 1 : 0;
        int r = node - itm * NU;
        float2* O2 = (float2*)out;
        float2 c0 = A2[base], c1 = A2[base + 32], c2 = A2[base + 64];
        float2 r0 = make_float2((c0.x + o0.x) * inv3, (c0.y + o0.y) * inv3);
        float2 r1 = make_float2((c1.x + o1.x) * inv3, (c1.y + o1.y) * inv3);
        float2 r2 = make_float2((c2.x + o2.x) * inv3, (c2.y + o2.y) * inv3);
        O2[(size_t)(0 + itm) * (NU * 32) + (size_t)r * 32 + lane] = r0;
        O2[(size_t)(2 + itm) * (NU * 32) + (size_t)r * 32 + lane] = r1;
        O2[(size_t)(4 + itm) * (NU * 32) + (size_t)r * 32 + lane] = r2;
    } else {
        X2[base] = o0; X2[base + 32] = o1; X2[base + 64] = o2;
        float2 c0 = A2[base];      c0.x += o0.x; c0.y += o0.y; A2[base] = c0;
        float2 c1 = A2[base + 32]; c1.x += o1.x; c1.y += o1.y; A2[base + 32] = c1;
        float2 c2 = A2[base + 64]; c2.x += o2.x; c2.y += o2.y; A2[base + 64] = c2;
    }
}

// ---------------- launch ------------------------------------------------------
extern "C" void kernel_launch(void* const* d_in, const int* in_sizes, int n_in,
                              void* d_out, int out_size) {
    const int* ei = (const int*)d_in[0];
    const float* v_feat = (const float*)d_in[1];
    const float* t_feat = (const float*)d_in[2];
    const float* user_emb = (const float*)d_in[3];
    const float* item_emb = (const float*)d_in[4];
    const float* user_emb_v = (const float*)d_in[5];
    const float* user_emb_t = (const float*)d_in[6];
    const float* W_v = (const float*)d_in[7];
    const float* b_v = (const float*)d_in[8];
    const float* W_t = (const float*)d_in[9];
    const float* b_t = (const float*)d_in[10];
    const float* W0 = (const float*)d_in[11];
    const float* b0 = (const float*)d_in[12];
    const float* W1 = (const float*)d_in[13];
    const float* b1 = (const float*)d_in[14];
    float* out = (float*)d_out;

    int E = in_sizes[0] / 2;
    if (E > EMAX) E = EMAX;

    // graph build
    k_deg_init<<<(NN + 255) / 256, 256>>>();
    k_count<<<(E + 255) / 256, 256>>>(ei, E);
    k_dinv<<<(NN + 255) / 256, 256>>>();
    k_scan1<<<NB_SCAN, 512>>>();
    k_scan2<<<1, 1>>>();
    k_scan3<<<NB_SCAN, 512>>>();
    k_fill<<<(E + 255) / 256, 256>>>(ei, E);

    // initial embeddings + projections (tensor cores)
    k_initX<<<(NU * 64 + 255) / 256, 256>>>(user_emb, user_emb_v, user_emb_t, item_emb);
    k_wgemm<0><<<(NU + 127) / 128, 256>>>(v_feat, NU, 2048, W_v, b_v);
    k_wgemm<1><<<(NU + 127) / 128, 256>>>(t_feat, NU, 768, W_t, b_t);

    // layer 0
    k_wgemm<2><<<(3 * NN + 127) / 128, 256>>>(nullptr, 3 * NN, 64, W0, nullptr);
    k_agg<0><<<(NN + 7) / 8, 256>>>(b0, nullptr);
    // layer 1 (fused output)
    k_wgemm<2><<<(3 * NN + 127) / 128, 256>>>(nullptr, 3 * NN, 64, W1, nullptr);
    k_agg<1><<<(NN + 7) / 8, 256>>>(b1, out);
}

// round 9
// speedup vs baseline: 1.9978x; 1.0883x over previous
#include <cuda_runtime.h>
#include <cuda_fp16.h>
#include <mma.h>
using namespace nvcuda;

#define NU 50000
#define NI 50000
#define NN 100000
#define DIM 64
#define EMAX 2000000
#define FW 192              // combined feature width: 3 stacks x 64
#define FW2 96              // in float2 / half2 units
#define NB_SCAN 196         // 196*512 >= 100000

// ---------------- device scratch (static; no dynamic allocation) -------------
__device__ int     g_deg[NN];                  // neighbor count (excl. self)
__device__ float   g_dinv[NN];
__device__ int     g_rowptr[NN];
__device__ int     g_cursor[NN];
__device__ int2    g_edges[2 * EMAX];          // (src, bitcast(dinv[src]))
__device__ __half2 g_Xh[(size_t)NN * FW2];     // layer input, fp16   (38.4 MB)
__device__ __half2 g_Hh[(size_t)NN * FW2];     // x @ W.T, fp16       (38.4 MB)
__device__ float   g_ACC[(size_t)NN * FW];     // running sum, fp32   (76.8 MB)
__device__ int     g_partial[NB_SCAN];

// ---------------- graph build ------------------------------------------------
__global__ void k_deg_zero() {
    int n = blockIdx.x * blockDim.x + threadIdx.x;
    if (n < NN) g_deg[n] = 0;
}

__global__ void k_count(const int* __restrict__ ei, int E) {
    int e = blockIdx.x * blockDim.x + threadIdx.x;
    if (e >= E) return;
    int u = ei[2 * e];
    int it = ei[2 * e + 1] + NU;
    atomicAdd(&g_deg[u], 1);
    atomicAdd(&g_deg[it], 1);
}

__global__ void k_scan1() {
    __shared__ int sh[512];
    int t = threadIdx.x;
    int idx = blockIdx.x * 512 + t;
    int v = (idx < NN) ? g_deg[idx] : 0;
    sh[t] = v;
    __syncthreads();
    for (int off = 256; off > 0; off >>= 1) {
        if (t < off) sh[t] += sh[t + off];
        __syncthreads();
    }
    if (t == 0) g_partial[blockIdx.x] = sh[0];
}

__global__ void k_scan2() {
    int run = 0;
    for (int b = 0; b < NB_SCAN; ++b) {
        int v = g_partial[b];
        g_partial[b] = run;
        run += v;
    }
}

__global__ void k_scan3() {   // exclusive scan + dinv (fused)
    __shared__ int sh[512];
    int t = threadIdx.x;
    int idx = blockIdx.x * 512 + t;
    int v = (idx < NN) ? g_deg[idx] : 0;
    sh[t] = v;
    __syncthreads();
    for (int off = 1; off < 512; off <<= 1) {
        int x = (t >= off) ? sh[t - off] : 0;
        __syncthreads();
        sh[t] += x;
        __syncthreads();
    }
    if (idx < NN) {
        int excl = g_partial[blockIdx.x] + sh[t] - v;
        g_rowptr[idx] = excl;
        g_cursor[idx] = excl;
        g_dinv[idx] = rsqrtf((float)(v + 1));   // +1 = self loop
    }
}

__global__ void k_fill(const int* __restrict__ ei, int E) {
    int e = blockIdx.x * blockDim.x + threadIdx.x;
    if (e >= E) return;
    int u = ei[2 * e];
    int it = ei[2 * e + 1] + NU;
    float du = g_dinv[u];
    float di = g_dinv[it];
    int p1 = atomicAdd(&g_cursor[it], 1);   // dst = item, src = user
    g_edges[p1] = make_int2(u, __float_as_int(du));
    int p2 = atomicAdd(&g_cursor[u], 1);    // dst = user, src = item
    g_edges[p2] = make_int2(it, __float_as_int(di));
}

// ---------------- init combined X (fp16) / ACC (fp32) ------------------------
__global__ void k_initX(const float* __restrict__ ue, const float* __restrict__ uev,
                        const float* __restrict__ uet, const float* __restrict__ ie) {
    int i = blockIdx.x * blockDim.x + threadIdx.x;     // over NU*32 (float2 cols)
    if (i >= NU * 32) return;
    int u = i >> 5;
    int c2 = i & 31;
    float2 a = ((const float2*)ue)[i];
    float2 b = ((const float2*)uev)[i];
    float2 d = ((const float2*)uet)[i];
    float2 e = ((const float2*)ie)[i];
    float2* A2 = (float2*)g_ACC;
    size_t ub = (size_t)u * FW2 + c2;
    g_Xh[ub]      = __floats2half2_rn(a.x, a.y);  A2[ub] = a;
    g_Xh[ub + 32] = __floats2half2_rn(b.x, b.y);  A2[ub + 32] = b;
    g_Xh[ub + 64] = __floats2half2_rn(d.x, d.y);  A2[ub + 64] = d;
    size_t ib = (size_t)(NU + u) * FW2 + c2;
    g_Xh[ib] = __floats2half2_rn(e.x, e.y);       A2[ib] = e;
}

// ---------------- projection GEMM (HMMA, register-prefetch pipelined) --------
// C(Mx64) = A(MxK) @ W(64xK)^T + bias ->  X fp16 slice + ACC fp32 slice (item rows)
// OUT_MODE 0: col offset 64 (v) ; OUT_MODE 1: col offset 128 (t)
#define LDA 40   // smem ld in halves
#define LDC 72   // smem ld in floats

template <int OUT_MODE>
__global__ void __launch_bounds__(256) k_wgemm_proj(const float* __restrict__ A, int M, int K,
                                                    const float* __restrict__ W,
                                                    const float* __restrict__ bias) {
    __shared__ __align__(16) char raw[128 * LDC * 4];   // 36864 B
    half*  As = (half*)raw;                   // [128][LDA]
    half*  Ws = (half*)(raw + 128 * LDA * 2); // [64][LDA]
    float* Cs = (float*)raw;                  // [128][LDC] (after K loop)

    int tid = threadIdx.x;
    int warp = tid >> 5;
    int rowBase = blockIdx.x * 128;

    wmma::fragment<wmma::accumulator, 16, 16, 16, float> acc[4];
#pragma unroll
    for (int nf = 0; nf < 4; ++nf) wmma::fill_fragment(acc[nf], 0.f);

    int lr = tid >> 1;               // 0..127 (A row)
    int lk = (tid & 1) * 16;         // 0/16   (A k base)
    bool rowOK = (rowBase + lr) < M;
    const float* Arow = A + (size_t)(rowBase + lr) * K + lk;

    float4 ra[4], rw[2];
    const float4 z4 = make_float4(0.f, 0.f, 0.f, 0.f);

#define LOAD_TILES(k0_)                                                     \
    {                                                                       \
        _Pragma("unroll")                                                   \
        for (int q = 0; q < 4; ++q)                                         \
            ra[q] = rowOK ? *(const float4*)(Arow + (k0_) + q * 4) : z4;    \
        _Pragma("unroll")                                                   \
        for (int it = 0; it < 2; ++it) {                                    \
            int f = tid + it * 256;                                         \
            int c = f >> 3;                                                 \
            int kq = (f & 7) * 4;                                           \
            rw[it] = *(const float4*)(W + (size_t)c * K + (k0_) + kq);      \
        }                                                                   \
    }

    LOAD_TILES(0);
    for (int k0 = 0; k0 < K; k0 += 32) {
        // commit staged registers -> smem (fp32 -> fp16)
        {
            half* da = As + lr * LDA + lk;
#pragma unroll
            for (int q = 0; q < 4; ++q) {
                *(half2*)(da + q * 4)     = __floats2half2_rn(ra[q].x, ra[q].y);
                *(half2*)(da + q * 4 + 2) = __floats2half2_rn(ra[q].z, ra[q].w);
            }
#pragma unroll
            for (int it = 0; it < 2; ++it) {
                int f = tid + it * 256;
                int c = f >> 3;
                int kq = (f & 7) * 4;
                half* dw = Ws + c * LDA + kq;
                *(half2*)(dw)     = __floats2half2_rn(rw[it].x, rw[it].y);
                *(half2*)(dw + 2) = __floats2half2_rn(rw[it].z, rw[it].w);
            }
        }
        __syncthreads();
        if (k0 + 32 < K) LOAD_TILES(k0 + 32);   // prefetch next while mma runs
#pragma unroll
        for (int kk = 0; kk < 32; kk += 16) {
            wmma::fragment<wmma::matrix_a, 16, 16, 16, half, wmma::row_major> af;
            wmma::load_matrix_sync(af, As + (warp * 16) * LDA + kk, LDA);
#pragma unroll
            for (int nf = 0; nf < 4; ++nf) {
                wmma::fragment<wmma::matrix_b, 16, 16, 16, half, wmma::col_major> bf;
                wmma::load_matrix_sync(bf, Ws + (nf * 16) * LDA + kk, LDA);
                wmma::mma_sync(acc[nf], af, bf, acc[nf]);
            }
        }
        __syncthreads();
    }

#pragma unroll
    for (int nf = 0; nf < 4; ++nf)
        wmma::store_matrix_sync(Cs + (warp * 16) * LDC + nf * 16, acc[nf], LDC, wmma::mem_row_major);
    __syncthreads();

    int r = tid >> 1;
    int h = (tid & 1) * 32;
    int gr = rowBase + r;
    if (gr < M) {
        const float* src = Cs + r * LDC + h;
        int node = NU + gr;
        int coff = (OUT_MODE == 0) ? 64 : 128;
        __half2* xo = g_Xh + (size_t)node * FW2 + (coff >> 1) + (h >> 1);
        float* ao = g_ACC + (size_t)node * FW + coff + h;
#pragma unroll
        for (int q = 0; q < 8; ++q) {
            float4 v = *(const float4*)(src + q * 4);
            v.x += __ldg(&bias[h + q * 4]);
            v.y += __ldg(&bias[h + q * 4 + 1]);
            v.z += __ldg(&bias[h + q * 4 + 2]);
            v.w += __ldg(&bias[h + q * 4 + 3]);
            *(float4*)(ao + q * 4) = v;
            xo[q * 2]     = __floats2half2_rn(v.x, v.y);
            xo[q * 2 + 1] = __floats2half2_rn(v.z, v.w);
        }
    }
}

// ---------------- dense layer GEMM: H = X @ W.T (fp16 in, fp16 out) ----------
// A = g_Xh viewed as [3*NN][64] halves; K = 64 (single smem tile, no loop)
#define LDH 72   // smem ld in halves

__global__ void __launch_bounds__(256) k_wgemm_dense(const float* __restrict__ W) {
    const int M = 3 * NN;
    __shared__ __align__(16) char raw[128 * LDC * 4];   // 36864 B
    half*  As = (half*)raw;                   // [128][LDH] 18432 B
    half*  Ws = (half*)(raw + 128 * LDH * 2); // [64][LDH]   9216 B
    float* Cs = (float*)raw;                  // [128][LDC]

    int tid = threadIdx.x;
    int warp = tid >> 5;
    int rowBase = blockIdx.x * 128;
    const half* Ah = (const half*)g_Xh;

    // A tile: 128 rows x 128 B, 16B chunks
#pragma unroll
    for (int it = 0; it < 4; ++it) {
        int c = tid + it * 256;         // 0..1023
        int r = c >> 3;
        int o = (c & 7) * 8;            // half offset
        int gr = rowBase + r;
        uint4 v = make_uint4(0, 0, 0, 0);
        if (gr < M) v = *(const uint4*)(Ah + (size_t)gr * 64 + o);
        *(uint4*)(As + r * LDH + o) = v;
    }
    // W tile: 64 x 64 fp32 -> fp16
    {
        int c = tid >> 2;
        int seg = (tid & 3) * 16;
        const float* wsrc = W + (size_t)c * 64 + seg;
        half* dw = Ws + c * LDH + seg;
#pragma unroll
        for (int q = 0; q < 4; ++q) {
            float4 v = *(const float4*)(wsrc + q * 4);
            *(half2*)(dw + q * 4)     = __floats2half2_rn(v.x, v.y);
            *(half2*)(dw + q * 4 + 2) = __floats2half2_rn(v.z, v.w);
        }
    }
    __syncthreads();

    wmma::fragment<wmma::accumulator, 16, 16, 16, float> acc[4];
#pragma unroll
    for (int nf = 0; nf < 4; ++nf) wmma::fill_fragment(acc[nf], 0.f);
#pragma unroll
    for (int kk = 0; kk < 64; kk += 16) {
        wmma::fragment<wmma::matrix_a, 16, 16, 16, half, wmma::row_major> af;
        wmma::load_matrix_sync(af, As + (warp * 16) * LDH + kk, LDH);
#pragma unroll
        for (int nf = 0; nf < 4; ++nf) {
            wmma::fragment<wmma::matrix_b, 16, 16, 16, half, wmma::col_major> bf;
            wmma::load_matrix_sync(bf, Ws + (nf * 16) * LDH + kk, LDH);
            wmma::mma_sync(acc[nf], af, bf, acc[nf]);
        }
    }
    __syncthreads();
#pragma unroll
    for (int nf = 0; nf < 4; ++nf)
        wmma::store_matrix_sync(Cs + (warp * 16) * LDC + nf * 16, acc[nf], LDC, wmma::mem_row_major);
    __syncthreads();

    int r = tid >> 1;
    int h = (tid & 1) * 32;
    int gr = rowBase + r;
    if (gr < M) {
        const float* src = Cs + r * LDC + h;
        __half2* Hrow = g_Hh + (size_t)gr * 32 + (h >> 1);
#pragma unroll
        for (int q = 0; q < 16; ++q)
            Hrow[q] = __floats2half2_rn(src[2 * q], src[2 * q + 1]);
    }
}

// ---------------- aggregation over fp16 H ------------------------------------
#define AGG_STEP(e)                                                     \
    {                                                                   \
        int s_ = (e).x;                                                 \
        float w_ = __int_as_float((e).y);                               \
        size_t sb_ = (size_t)s_ * FW2 + lane;                           \
        float2 v0_ = __half22float2(__ldg(&g_Hh[sb_]));                 \
        float2 v1_ = __half22float2(__ldg(&g_Hh[sb_ + 32]));            \
        float2 v2_ = __half22float2(__ldg(&g_Hh[sb_ + 64]));            \
        a0x += w_ * v0_.x; a0y += w_ * v0_.y;                           \
        a1x += w_ * v1_.x; a1y += w_ * v1_.y;                           \
        a2x += w_ * v2_.x; a2y += w_ * v2_.y;                           \
    }

template <int FINAL>
__global__ void __launch_bounds__(256) k_agg(const float* __restrict__ bias,
                                             float* __restrict__ out) {
    int warp = threadIdx.x >> 5;
    int lane = threadIdx.x & 31;
    int node = blockIdx.x * 8 + warp;
    if (node >= NN) return;

    float2* A2 = (float2*)g_ACC;

    float dn = g_dinv[node];
    size_t base = (size_t)node * FW2 + lane;

    // self-loop (weight dinv; outer dinv at end -> dinv^2)
    float2 h0 = __half22float2(__ldg(&g_Hh[base]));
    float2 h1 = __half22float2(__ldg(&g_Hh[base + 32]));
    float2 h2 = __half22float2(__ldg(&g_Hh[base + 64]));
    float a0x = dn * h0.x, a0y = dn * h0.y;
    float a1x = dn * h1.x, a1y = dn * h1.y;
    float a2x = dn * h2.x, a2y = dn * h2.y;

    int p = g_rowptr[node];
    int cnt = g_deg[node];

    int j = 0;
    for (; j + 4 <= cnt; j += 4) {
        int2 e0 = __ldg(&g_edges[p + j]);
        int2 e1 = __ldg(&g_edges[p + j + 1]);
        int2 e2 = __ldg(&g_edges[p + j + 2]);
        int2 e3 = __ldg(&g_edges[p + j + 3]);
        AGG_STEP(e0); AGG_STEP(e1); AGG_STEP(e2); AGG_STEP(e3);
    }
    for (; j < cnt; ++j) {
        int2 e = __ldg(&g_edges[p + j]);
        AGG_STEP(e);
    }

    float bx = __ldg(&bias[2 * lane]);
    float by = __ldg(&bias[2 * lane + 1]);
    float2 o0 = make_float2(a0x * dn + bx, a0y * dn + by);
    float2 o1 = make_float2(a1x * dn + bx, a1y * dn + by);
    float2 o2 = make_float2(a2x * dn + bx, a2y * dn + by);

    if (FINAL) {
        const float inv3 = 1.f / 3.f;
        int itm = (node >= NU) ? 1 : 0;
        int r = node - itm * NU;
        float2* O2 = (float2*)out;
        float2 c0 = A2[base], c1 = A2[base + 32], c2 = A2[base + 64];
        float2 r0 = make_float2((c0.x + o0.x) * inv3, (c0.y + o0.y) * inv3);
        float2 r1 = make_float2((c1.x + o1.x) * inv3, (c1.y + o1.y) * inv3);
        float2 r2 = make_float2((c2.x + o2.x) * inv3, (c2.y + o2.y) * inv3);
        O2[(size_t)(0 + itm) * (NU * 32) + (size_t)r * 32 + lane] = r0;
        O2[(size_t)(2 + itm) * (NU * 32) + (size_t)r * 32 + lane] = r1;
        O2[(size_t)(4 + itm) * (NU * 32) + (size_t)r * 32 + lane] = r2;
    } else {
        g_Xh[base]      = __floats2half2_rn(o0.x, o0.y);
        g_Xh[base + 32] = __floats2half2_rn(o1.x, o1.y);
        g_Xh[base + 64] = __floats2half2_rn(o2.x, o2.y);
        float2 c0 = A2[base];      c0.x += o0.x; c0.y += o0.y; A2[base] = c0;
        float2 c1 = A2[base + 32]; c1.x += o1.x; c1.y += o1.y; A2[base + 32] = c1;
        float2 c2 = A2[base + 64]; c2.x += o2.x; c2.y += o2.y; A2[base + 64] = c2;
    }
}

// ---------------- launch ------------------------------------------------------
extern "C" void kernel_launch(void* const* d_in, const int* in_sizes, int n_in,
                              void* d_out, int out_size) {
    const int* ei = (const int*)d_in[0];
    const float* v_feat = (const float*)d_in[1];
    const float* t_feat = (const float*)d_in[2];
    const float* user_emb = (const float*)d_in[3];
    const float* item_emb = (const float*)d_in[4];
    const float* user_emb_v = (const float*)d_in[5];
    const float* user_emb_t = (const float*)d_in[6];
    const float* W_v = (const float*)d_in[7];
    const float* b_v = (const float*)d_in[8];
    const float* W_t = (const float*)d_in[9];
    const float* b_t = (const float*)d_in[10];
    const float* W0 = (const float*)d_in[11];
    const float* b0 = (const float*)d_in[12];
    const float* W1 = (const float*)d_in[13];
    const float* b1 = (const float*)d_in[14];
    float* out = (float*)d_out;

    int E = in_sizes[0] / 2;
    if (E > EMAX) E = EMAX;

    // lazy infra (created on the uncaptured correctness call; reused thereafter)
    static cudaStream_t sT = nullptr, sG = nullptr;
    static cudaEvent_t evRoot = nullptr, evT = nullptr, evG = nullptr;
    if (sT == nullptr) {
        cudaStreamCreateWithFlags(&sT, cudaStreamNonBlocking);
        cudaStreamCreateWithFlags(&sG, cudaStreamNonBlocking);
        cudaEventCreateWithFlags(&evRoot, cudaEventDisableTiming);
        cudaEventCreateWithFlags(&evT, cudaEventDisableTiming);
        cudaEventCreateWithFlags(&evG, cudaEventDisableTiming);
    }

    // fork side streams off the main (capture) stream
    cudaEventRecord(evRoot, 0);
    cudaStreamWaitEvent(sG, evRoot, 0);
    cudaStreamWaitEvent(sT, evRoot, 0);

    // sG: graph build (independent of everything else)
    k_deg_zero<<<(NN + 255) / 256, 256, 0, sG>>>();
    k_count<<<(E + 255) / 256, 256, 0, sG>>>(ei, E);
    k_scan1<<<NB_SCAN, 512, 0, sG>>>();
    k_scan2<<<1, 1, 0, sG>>>();
    k_scan3<<<NB_SCAN, 512, 0, sG>>>();
    k_fill<<<(E + 255) / 256, 256, 0, sG>>>(ei, E);
    cudaEventRecord(evG, sG);

    // sT: t projection (independent of initX / v-projection)
    k_wgemm_proj<1><<<(NU + 127) / 128, 256, 0, sT>>>(t_feat, NU, 768, W_t, b_t);
    cudaEventRecord(evT, sT);

    // main: initX + v projection
    k_initX<<<(NU * 32 + 255) / 256, 256>>>(user_emb, user_emb_v, user_emb_t, item_emb);
    k_wgemm_proj<0><<<(NU + 127) / 128, 256>>>(v_feat, NU, 2048, W_v, b_v);

    // join t projection, then layer 0 dense
    cudaStreamWaitEvent(0, evT, 0);
    k_wgemm_dense<<<(3 * NN + 127) / 128, 256>>>(W0);

    // join graph build, then aggregate layer 0
    cudaStreamWaitEvent(0, evG, 0);
    k_agg<0><<<(NN + 7) / 8, 256>>>(b0, nullptr);

    // layer 1 (fused output)
    k_wgemm_dense<<<(3 * NN + 127) / 128, 256>>>(W1);
    k_agg<1><<<(NN + 7) / 8, 256>>>(b1, out);
}

// round 10
// speedup vs baseline: 2.2770x; 1.1397x over previous
#include <cuda_runtime.h>
#include <cuda_fp16.h>
#include <mma.h>
using namespace nvcuda;

#define NU 50000
#define NI 50000
#define NN 100000
#define DIM 64
#define EMAX 2000000
#define FW 192              // combined feature width: 3 stacks x 64
#define FW2 96              // in half2 units
#define NB_SCAN 196         // 196*512 >= 100000
#define DSPLIT 149888       // 1171*128 : dense-L0 user/item row split (rows < 3*NU)

// ---------------- device scratch (static; no dynamic allocation) -------------
__device__ int     g_deg[NN];                  // neighbor count (excl. self)
__device__ float   g_dinv[NN];
__device__ int     g_rowptr[NN];
__device__ int     g_cursor[NN];
__device__ int2    g_edges[2 * EMAX];          // (src, bitcast(dinv[src]))
__device__ __half2 g_X0h[(size_t)NN * FW2];    // layer-0 input (kept for output), fp16
__device__ __half2 g_Xh[(size_t)NN * FW2];     // current layer input, fp16
__device__ __half2 g_Hh[(size_t)NN * FW2];     // x @ W.T, fp16 (L2-resident)
__device__ int     g_partial[NB_SCAN];

__device__ __forceinline__ unsigned h2u(__half2 h) { return *reinterpret_cast<unsigned*>(&h); }

// ---------------- graph build ------------------------------------------------
__global__ void k_deg_zero() {
    int n = blockIdx.x * blockDim.x + threadIdx.x;
    if (n < NN) g_deg[n] = 0;
}

__global__ void k_count(const int* __restrict__ ei, int E) {
    int e = blockIdx.x * blockDim.x + threadIdx.x;
    if (e >= E) return;
    int u = ei[2 * e];
    int it = ei[2 * e + 1] + NU;
    atomicAdd(&g_deg[u], 1);
    atomicAdd(&g_deg[it], 1);
}

__global__ void k_scan1() {
    __shared__ int sh[512];
    int t = threadIdx.x;
    int idx = blockIdx.x * 512 + t;
    int v = (idx < NN) ? g_deg[idx] : 0;
    sh[t] = v;
    __syncthreads();
    for (int off = 256; off > 0; off >>= 1) {
        if (t < off) sh[t] += sh[t + off];
        __syncthreads();
    }
    if (t == 0) g_partial[blockIdx.x] = sh[0];
}

__global__ void k_scan2() {      // 256-thread single-block exclusive scan of 196 partials
    __shared__ int sh[256];
    int t = threadIdx.x;
    int v = (t < NB_SCAN) ? g_partial[t] : 0;
    sh[t] = v;
    __syncthreads();
    for (int off = 1; off < 256; off <<= 1) {
        int x = (t >= off) ? sh[t - off] : 0;
        __syncthreads();
        sh[t] += x;
        __syncthreads();
    }
    if (t < NB_SCAN) g_partial[t] = sh[t] - v;
}

__global__ void k_scan3() {   // exclusive scan + dinv (fused)
    __shared__ int sh[512];
    int t = threadIdx.x;
    int idx = blockIdx.x * 512 + t;
    int v = (idx < NN) ? g_deg[idx] : 0;
    sh[t] = v;
    __syncthreads();
    for (int off = 1; off < 512; off <<= 1) {
        int x = (t >= off) ? sh[t - off] : 0;
        __syncthreads();
        sh[t] += x;
        __syncthreads();
    }
    if (idx < NN) {
        int excl = g_partial[blockIdx.x] + sh[t] - v;
        g_rowptr[idx] = excl;
        g_cursor[idx] = excl;
        g_dinv[idx] = rsqrtf((float)(v + 1));   // +1 = self loop
    }
}

__global__ void k_fill(const int* __restrict__ ei, int E) {
    int e = blockIdx.x * blockDim.x + threadIdx.x;
    if (e >= E) return;
    int u = ei[2 * e];
    int it = ei[2 * e + 1] + NU;
    float du = g_dinv[u];
    float di = g_dinv[it];
    int p1 = atomicAdd(&g_cursor[it], 1);   // dst = item, src = user
    g_edges[p1] = make_int2(u, __float_as_int(du));
    int p2 = atomicAdd(&g_cursor[u], 1);    // dst = user, src = item
    g_edges[p2] = make_int2(it, __float_as_int(di));
}

// ---------------- init combined X0 / X (both fp16) ---------------------------
__global__ void k_initX(const float* __restrict__ ue, const float* __restrict__ uev,
                        const float* __restrict__ uet, const float* __restrict__ ie) {
    int i = blockIdx.x * blockDim.x + threadIdx.x;     // over NU*32 (half2 cols)
    if (i >= NU * 32) return;
    int u = i >> 5;
    int c2 = i & 31;
    float2 a = ((const float2*)ue)[i];
    float2 b = ((const float2*)uev)[i];
    float2 d = ((const float2*)uet)[i];
    float2 e = ((const float2*)ie)[i];
    size_t ub = (size_t)u * FW2 + c2;
    __half2 ha = __floats2half2_rn(a.x, a.y);
    __half2 hb = __floats2half2_rn(b.x, b.y);
    __half2 hd = __floats2half2_rn(d.x, d.y);
    __half2 he = __floats2half2_rn(e.x, e.y);
    g_Xh[ub] = ha;       g_X0h[ub] = ha;
    g_Xh[ub + 32] = hb;  g_X0h[ub + 32] = hb;
    g_Xh[ub + 64] = hd;  g_X0h[ub + 64] = hd;
    size_t ib = (size_t)(NU + u) * FW2 + c2;
    g_Xh[ib] = he;       g_X0h[ib] = he;
}

// ---------------- projection GEMM (HMMA, register-prefetch pipelined) --------
// C(Mx64) = A(MxK) @ W(64xK)^T + bias ->  Xh + X0h fp16 item slices
// OUT_MODE 0: col offset 64 (v) ; OUT_MODE 1: col offset 128 (t)
#define LDA 40    // smem ld in halves
#define LDC2 20   // epilogue staging ld in floats (16 cols + pad)

template <int OUT_MODE>
__global__ void __launch_bounds__(256) k_wgemm_proj(const float* __restrict__ A, int M, int K,
                                                    const float* __restrict__ W,
                                                    const float* __restrict__ bias) {
    __shared__ __align__(16) char raw[128 * LDA * 2 + 64 * LDA * 2];   // 15360 B
    half*  As = (half*)raw;                   // [128][LDA]
    half*  Ws = (half*)(raw + 128 * LDA * 2); // [64][LDA]
    float* Cs = (float*)raw;                  // [128][LDC2] (overlaps A after K loop)

    int tid = threadIdx.x;
    int warp = tid >> 5;
    int rowBase = blockIdx.x * 128;

    wmma::fragment<wmma::accumulator, 16, 16, 16, float> acc[4];
#pragma unroll
    for (int nf = 0; nf < 4; ++nf) wmma::fill_fragment(acc[nf], 0.f);

    int lr = tid >> 1;               // 0..127 (A row)
    int lk = (tid & 1) * 16;         // 0/16   (A k base)
    bool rowOK = (rowBase + lr) < M;
    const float* Arow = A + (size_t)(rowBase + lr) * K + lk;

    float4 ra[4], rw[2];
    const float4 z4 = make_float4(0.f, 0.f, 0.f, 0.f);

#define LOAD_TILES(k0_)                                                     \
    {                                                                       \
        _Pragma("unroll")                                                   \
        for (int q = 0; q < 4; ++q)                                         \
            ra[q] = rowOK ? *(const float4*)(Arow + (k0_) + q * 4) : z4;    \
        _Pragma("unroll")                                                   \
        for (int it = 0; it < 2; ++it) {                                    \
            int f = tid + it * 256;                                         \
            int c = f >> 3;                                                 \
            int kq = (f & 7) * 4;                                           \
            rw[it] = *(const float4*)(W + (size_t)c * K + (k0_) + kq);      \
        }                                                                   \
    }

    LOAD_TILES(0);
    for (int k0 = 0; k0 < K; k0 += 32) {
        {
            half* da = As + lr * LDA + lk;
#pragma unroll
            for (int q = 0; q < 4; ++q) {
                *(half2*)(da + q * 4)     = __floats2half2_rn(ra[q].x, ra[q].y);
                *(half2*)(da + q * 4 + 2) = __floats2half2_rn(ra[q].z, ra[q].w);
            }
#pragma unroll
            for (int it = 0; it < 2; ++it) {
                int f = tid + it * 256;
                int c = f >> 3;
                int kq = (f & 7) * 4;
                half* dw = Ws + c * LDA + kq;
                *(half2*)(dw)     = __floats2half2_rn(rw[it].x, rw[it].y);
                *(half2*)(dw + 2) = __floats2half2_rn(rw[it].z, rw[it].w);
            }
        }
        __syncthreads();
        if (k0 + 32 < K) LOAD_TILES(k0 + 32);   // prefetch next while mma runs
#pragma unroll
        for (int kk = 0; kk < 32; kk += 16) {
            wmma::fragment<wmma::matrix_a, 16, 16, 16, half, wmma::row_major> af;
            wmma::load_matrix_sync(af, As + (warp * 16) * LDA + kk, LDA);
#pragma unroll
            for (int nf = 0; nf < 4; ++nf) {
                wmma::fragment<wmma::matrix_b, 16, 16, 16, half, wmma::col_major> bf;
                wmma::load_matrix_sync(bf, Ws + (nf * 16) * LDA + kk, LDA);
                wmma::mma_sync(acc[nf], af, bf, acc[nf]);
            }
        }
        __syncthreads();
    }

    // epilogue, staged 16 cols at a time through small smem
    int r = tid >> 1;
    int c8 = (tid & 1) * 8;
    int gr = rowBase + r;
    int coff = (OUT_MODE == 0) ? 64 : 128;
#pragma unroll
    for (int nf = 0; nf < 4; ++nf) {
        wmma::store_matrix_sync(Cs + (warp * 16) * LDC2, acc[nf], LDC2, wmma::mem_row_major);
        __syncthreads();
        if (gr < M) {
            const float* src = Cs + r * LDC2 + c8;
            int cbase = nf * 16 + c8;
            __half2 h[4];
#pragma unroll
            for (int q = 0; q < 4; ++q) {
                float vx = src[2 * q]     + __ldg(&bias[cbase + 2 * q]);
                float vy = src[2 * q + 1] + __ldg(&bias[cbase + 2 * q + 1]);
                h[q] = __floats2half2_rn(vx, vy);
            }
            uint4 u = make_uint4(h2u(h[0]), h2u(h[1]), h2u(h[2]), h2u(h[3]));
            size_t o = (size_t)(NU + gr) * FW2 + ((coff + cbase) >> 1);
            *(uint4*)(g_Xh + o)  = u;
            *(uint4*)(g_X0h + o) = u;
        }
        __syncthreads();
    }
}

// ---------------- dense layer GEMM: H = X @ W.T (fp16 in, fp16 out) ----------
// A = g_Xh viewed as [3*NN][64] halves; rows [rowStart, rowStart+rowCnt)
#define LDH 72   // smem ld in halves

__global__ void __launch_bounds__(256) k_wgemm_dense(const float* __restrict__ W, int rowStart) {
    const int M = 3 * NN;
    __shared__ __align__(16) char raw[128 * LDH * 2 + 64 * LDH * 2];   // 27648 B
    half*  As = (half*)raw;                   // [128][LDH]
    half*  Ws = (half*)(raw + 128 * LDH * 2); // [64][LDH]
    float* Cs = (float*)raw;                  // [128][LDC2]

    int tid = threadIdx.x;
    int warp = tid >> 5;
    int rowBase = rowStart + blockIdx.x * 128;
    const half* Ah = (const half*)g_Xh;

#pragma unroll
    for (int it = 0; it < 4; ++it) {
        int c = tid + it * 256;         // 0..1023
        int r = c >> 3;
        int o = (c & 7) * 8;            // half offset
        int gr = rowBase + r;
        uint4 v = make_uint4(0, 0, 0, 0);
        if (gr < M) v = *(const uint4*)(Ah + (size_t)gr * 64 + o);
        *(uint4*)(As + r * LDH + o) = v;
    }
    {
        int c = tid >> 2;
        int seg = (tid & 3) * 16;
        const float* wsrc = W + (size_t)c * 64 + seg;
        half* dw = Ws + c * LDH + seg;
#pragma unroll
        for (int q = 0; q < 4; ++q) {
            float4 v = *(const float4*)(wsrc + q * 4);
            *(half2*)(dw + q * 4)     = __floats2half2_rn(v.x, v.y);
            *(half2*)(dw + q * 4 + 2) = __floats2half2_rn(v.z, v.w);
        }
    }
    __syncthreads();

    wmma::fragment<wmma::accumulator, 16, 16, 16, float> acc[4];
#pragma unroll
    for (int nf = 0; nf < 4; ++nf) wmma::fill_fragment(acc[nf], 0.f);
#pragma unroll
    for (int kk = 0; kk < 64; kk += 16) {
        wmma::fragment<wmma::matrix_a, 16, 16, 16, half, wmma::row_major> af;
        wmma::load_matrix_sync(af, As + (warp * 16) * LDH + kk, LDH);
#pragma unroll
        for (int nf = 0; nf < 4; ++nf) {
            wmma::fragment<wmma::matrix_b, 16, 16, 16, half, wmma::col_major> bf;
            wmma::load_matrix_sync(bf, Ws + (nf * 16) * LDH + kk, LDH);
            wmma::mma_sync(acc[nf], af, bf, acc[nf]);
        }
    }
    __syncthreads();

    int r = tid >> 1;
    int c8 = (tid & 1) * 8;
    int gr = rowBase + r;
#pragma unroll
    for (int nf = 0; nf < 4; ++nf) {
        wmma::store_matrix_sync(Cs + (warp * 16) * LDC2, acc[nf], LDC2, wmma::mem_row_major);
        __syncthreads();
        if (gr < M) {
            const float* src = Cs + r * LDC2 + c8;
            __half2 h[4];
#pragma unroll
            for (int q = 0; q < 4; ++q)
                h[q] = __floats2half2_rn(src[2 * q], src[2 * q + 1]);
            uint4 u = make_uint4(h2u(h[0]), h2u(h[1]), h2u(h[2]), h2u(h[3]));
            *(uint4*)(g_Hh + (size_t)gr * 32 + ((nf * 16 + c8) >> 1)) = u;
        }
        __syncthreads();
    }
}

// ---------------- aggregation over fp16 H ------------------------------------
// x_new = dinv[dst]*(sum w*H[src] + dinv[dst]*H[dst]) + b
// FINAL=0: Xh = x_new
// FINAL=1: out[section] = (X0 + X1 + x_new)/3
#define AGG_STEP(e)                                                     \
    {                                                                   \
        int s_ = (e).x;                                                 \
        float w_ = __int_as_float((e).y);                               \
        size_t sb_ = (size_t)s_ * FW2 + lane;                           \
        float2 v0_ = __half22float2(__ldg(&g_Hh[sb_]));                 \
        float2 v1_ = __half22float2(__ldg(&g_Hh[sb_ + 32]));            \
        float2 v2_ = __half22float2(__ldg(&g_Hh[sb_ + 64]));            \
        a0x += w_ * v0_.x; a0y += w_ * v0_.y;                           \
        a1x += w_ * v1_.x; a1y += w_ * v1_.y;                           \
        a2x += w_ * v2_.x; a2y += w_ * v2_.y;                           \
    }

template <int FINAL>
__global__ void __launch_bounds__(256) k_agg(const float* __restrict__ bias,
                                             float* __restrict__ out) {
    int warp = threadIdx.x >> 5;
    int lane = threadIdx.x & 31;
    int node = blockIdx.x * 8 + warp;
    if (node >= NN) return;

    float dn = g_dinv[node];
    size_t base = (size_t)node * FW2 + lane;

    // self-loop (weight dinv; outer dinv at end -> dinv^2)
    float2 h0 = __half22float2(__ldg(&g_Hh[base]));
    float2 h1 = __half22float2(__ldg(&g_Hh[base + 32]));
    float2 h2 = __half22float2(__ldg(&g_Hh[base + 64]));
    float a0x = dn * h0.x, a0y = dn * h0.y;
    float a1x = dn * h1.x, a1y = dn * h1.y;
    float a2x = dn * h2.x, a2y = dn * h2.y;

    int p = g_rowptr[node];
    int cnt = g_deg[node];

    int j = 0;
    for (; j + 4 <= cnt; j += 4) {
        int2 e0 = __ldg(&g_edges[p + j]);
        int2 e1 = __ldg(&g_edges[p + j + 1]);
        int2 e2 = __ldg(&g_edges[p + j + 2]);
        int2 e3 = __ldg(&g_edges[p + j + 3]);
        AGG_STEP(e0); AGG_STEP(e1); AGG_STEP(e2); AGG_STEP(e3);
    }
    for (; j < cnt; ++j) {
        int2 e = __ldg(&g_edges[p + j]);
        AGG_STEP(e);
    }

    float bx = __ldg(&bias[2 * lane]);
    float by = __ldg(&bias[2 * lane + 1]);
    float2 o0 = make_float2(a0x * dn + bx, a0y * dn + by);
    float2 o1 = make_float2(a1x * dn + bx, a1y * dn + by);
    float2 o2 = make_float2(a2x * dn + bx, a2y * dn + by);

    if (FINAL) {
        const float inv3 = 1.f / 3.f;
        int itm = (node >= NU) ? 1 : 0;
        int r = node - itm * NU;
        float2* O2 = (float2*)out;
        float2 x00 = __half22float2(g_X0h[base]);
        float2 x01 = __half22float2(g_X0h[base + 32]);
        float2 x02 = __half22float2(g_X0h[base + 64]);
        float2 x10 = __half22float2(g_Xh[base]);
        float2 x11 = __half22float2(g_Xh[base + 32]);
        float2 x12 = __half22float2(g_Xh[base + 64]);
        float2 r0 = make_float2((x00.x + x10.x + o0.x) * inv3, (x00.y + x10.y + o0.y) * inv3);
        float2 r1 = make_float2((x01.x + x11.x + o1.x) * inv3, (x01.y + x11.y + o1.y) * inv3);
        float2 r2 = make_float2((x02.x + x12.x + o2.x) * inv3, (x02.y + x12.y + o2.y) * inv3);
        O2[(size_t)(0 + itm) * (NU * 32) + (size_t)r * 32 + lane] = r0;
        O2[(size_t)(2 + itm) * (NU * 32) + (size_t)r * 32 + lane] = r1;
        O2[(size_t)(4 + itm) * (NU * 32) + (size_t)r * 32 + lane] = r2;
    } else {
        g_Xh[base]      = __floats2half2_rn(o0.x, o0.y);
        g_Xh[base + 32] = __floats2half2_rn(o1.x, o1.y);
        g_Xh[base + 64] = __floats2half2_rn(o2.x, o2.y);
    }
}

// ---------------- launch ------------------------------------------------------
extern "C" void kernel_launch(void* const* d_in, const int* in_sizes, int n_in,
                              void* d_out, int out_size) {
    const int* ei = (const int*)d_in[0];
    const float* v_feat = (const float*)d_in[1];
    const float* t_feat = (const float*)d_in[2];
    const float* user_emb = (const float*)d_in[3];
    const float* item_emb = (const float*)d_in[4];
    const float* user_emb_v = (const float*)d_in[5];
    const float* user_emb_t = (const float*)d_in[6];
    const float* W_v = (const float*)d_in[7];
    const float* b_v = (const float*)d_in[8];
    const float* W_t = (const float*)d_in[9];
    const float* b_t = (const float*)d_in[10];
    const float* W0 = (const float*)d_in[11];
    const float* b0 = (const float*)d_in[12];
    const float* W1 = (const float*)d_in[13];
    const float* b1 = (const float*)d_in[14];
    float* out = (float*)d_out;

    int E = in_sizes[0] / 2;
    if (E > EMAX) E = EMAX;

    // lazy infra (created on the uncaptured correctness call; reused thereafter)
    static cudaStream_t sT = nullptr, sG = nullptr;
    static cudaEvent_t evRoot = nullptr, evT = nullptr, evG = nullptr, evInit = nullptr;
    if (sT == nullptr) {
        cudaStreamCreateWithFlags(&sT, cudaStreamNonBlocking);
        cudaStreamCreateWithFlags(&sG, cudaStreamNonBlocking);
        cudaEventCreateWithFlags(&evRoot, cudaEventDisableTiming);
        cudaEventCreateWithFlags(&evT, cudaEventDisableTiming);
        cudaEventCreateWithFlags(&evG, cudaEventDisableTiming);
        cudaEventCreateWithFlags(&evInit, cudaEventDisableTiming);
    }

    // fork side streams off the main (capture) stream
    cudaEventRecord(evRoot, 0);
    cudaStreamWaitEvent(sG, evRoot, 0);
    cudaStreamWaitEvent(sT, evRoot, 0);

    // sG: graph build (independent of everything else)
    k_deg_zero<<<(NN + 255) / 256, 256, 0, sG>>>();
    k_count<<<(E + 255) / 256, 256, 0, sG>>>(ei, E);
    k_scan1<<<NB_SCAN, 512, 0, sG>>>();
    k_scan2<<<1, 256, 0, sG>>>();
    k_scan3<<<NB_SCAN, 512, 0, sG>>>();
    k_fill<<<(E + 255) / 256, 256, 0, sG>>>(ei, E);
    cudaEventRecord(evG, sG);

    // main: initX
    k_initX<<<(NU * 32 + 255) / 256, 256>>>(user_emb, user_emb_v, user_emb_t, item_emb);
    cudaEventRecord(evInit, 0);

    // sT: t projection, then dense-L0 user rows (need only initX)
    k_wgemm_proj<1><<<(NU + 127) / 128, 256, 0, sT>>>(t_feat, NU, 768, W_t, b_t);
    cudaStreamWaitEvent(sT, evInit, 0);
    k_wgemm_dense<<<DSPLIT / 128, 256, 0, sT>>>(W0, 0);
    cudaEventRecord(evT, sT);

    // main: v projection (big one)
    k_wgemm_proj<0><<<(NU + 127) / 128, 256>>>(v_feat, NU, 2048, W_v, b_v);

    // join sT, then dense-L0 item rows
    cudaStreamWaitEvent(0, evT, 0);
    k_wgemm_dense<<<(3 * NN - DSPLIT + 127) / 128, 256>>>(W0, DSPLIT);

    // join graph build, then aggregate layer 0
    cudaStreamWaitEvent(0, evG, 0);
    k_agg<0><<<(NN + 7) / 8, 256>>>(b0, nullptr);

    // layer 1 (fused output)
    k_wgemm_dense<<<(3 * NN + 127) / 128, 256>>>(W1, 0);
    k_agg<1><<<(NN + 7) / 8, 256>>>(b1, out);
}

// round 12
// speedup vs baseline: 2.3602x; 1.0366x over previous
#include <cuda_runtime.h>
#include <cuda_fp16.h>
#include <mma.h>
using namespace nvcuda;

#define NU 50000
#define NI 50000
#define NN 100000
#define DIM 64
#define EMAX 2000000
#define FW 192              // combined feature width: 3 stacks x 64
#define FW2 96              // in half2 units
#define NB_SCAN 196         // 196*512 >= 100000
#define DSPLIT 149888       // 1171*128 : dense user/item row split (< 3*NU)
#define NA 50000            // agg0 first-half node count

// ---------------- device scratch (static; no dynamic allocation) -------------
__device__ int     g_deg[NN];                  // neighbor count (excl. self)
__device__ float   g_dinv[NN];
__device__ int     g_rowptr[NN];
__device__ int     g_cursor[NN];
__device__ int2    g_edges[2 * EMAX];          // (src, bitcast(dinv[src]))
__device__ __half2 g_X0h[(size_t)NN * FW2];    // layer-0 input (kept for output), fp16
__device__ __half2 g_Xh[(size_t)NN * FW2];     // current layer input, fp16
__device__ __half2 g_Hh0[(size_t)NN * FW2];    // layer-0 dense output, fp16
__device__ __half2 g_Hh1[(size_t)NN * FW2];    // layer-1 dense output, fp16
__device__ int     g_partial[NB_SCAN];

__device__ __forceinline__ unsigned h2u(__half2 h) { return *reinterpret_cast<unsigned*>(&h); }

// ---------------- graph build ------------------------------------------------
__global__ void k_deg_zero() {
    int n = blockIdx.x * blockDim.x + threadIdx.x;
    if (n < NN) g_deg[n] = 0;
}

__global__ void k_count(const int* __restrict__ ei, int E) {
    int e = blockIdx.x * blockDim.x + threadIdx.x;
    if (e >= E) return;
    int u = ei[2 * e];
    int it = ei[2 * e + 1] + NU;
    atomicAdd(&g_deg[u], 1);
    atomicAdd(&g_deg[it], 1);
}

__global__ void k_scan1() {
    __shared__ int sh[512];
    int t = threadIdx.x;
    int idx = blockIdx.x * 512 + t;
    int v = (idx < NN) ? g_deg[idx] : 0;
    sh[t] = v;
    __syncthreads();
    for (int off = 256; off > 0; off >>= 1) {
        if (t < off) sh[t] += sh[t + off];
        __syncthreads();
    }
    if (t == 0) g_partial[blockIdx.x] = sh[0];
}

__global__ void k_scan2() {      // 256-thread single-block exclusive scan of partials
    __shared__ int sh[256];
    int t = threadIdx.x;
    int v = (t < NB_SCAN) ? g_partial[t] : 0;
    sh[t] = v;
    __syncthreads();
    for (int off = 1; off < 256; off <<= 1) {
        int x = (t >= off) ? sh[t - off] : 0;
        __syncthreads();
        sh[t] += x;
        __syncthreads();
    }
    if (t < NB_SCAN) g_partial[t] = sh[t] - v;
}

__global__ void k_scan3() {   // exclusive scan + dinv (fused)
    __shared__ int sh[512];
    int t = threadIdx.x;
    int idx = blockIdx.x * 512 + t;
    int v = (idx < NN) ? g_deg[idx] : 0;
    sh[t] = v;
    __syncthreads();
    for (int off = 1; off < 512; off <<= 1) {
        int x = (t >= off) ? sh[t - off] : 0;
        __syncthreads();
        sh[t] += x;
        __syncthreads();
    }
    if (idx < NN) {
        int excl = g_partial[blockIdx.x] + sh[t] - v;
        g_rowptr[idx] = excl;
        g_cursor[idx] = excl;
        g_dinv[idx] = rsqrtf((float)(v + 1));   // +1 = self loop
    }
}

__global__ void k_fill(const int* __restrict__ ei, int E) {
    int e = blockIdx.x * blockDim.x + threadIdx.x;
    if (e >= E) return;
    int u = ei[2 * e];
    int it = ei[2 * e + 1] + NU;
    float du = g_dinv[u];
    float di = g_dinv[it];
    int p1 = atomicAdd(&g_cursor[it], 1);   // dst = item, src = user
    g_edges[p1] = make_int2(u, __float_as_int(du));
    int p2 = atomicAdd(&g_cursor[u], 1);    // dst = user, src = item
    g_edges[p2] = make_int2(it, __float_as_int(di));
}

// ---------------- init combined X0 / X (both fp16) ---------------------------
__global__ void k_initX(const float* __restrict__ ue, const float* __restrict__ uev,
                        const float* __restrict__ uet, const float* __restrict__ ie) {
    int i = blockIdx.x * blockDim.x + threadIdx.x;     // over NU*32 (half2 cols)
    if (i >= NU * 32) return;
    int u = i >> 5;
    int c2 = i & 31;
    float2 a = ((const float2*)ue)[i];
    float2 b = ((const float2*)uev)[i];
    float2 d = ((const float2*)uet)[i];
    float2 e = ((const float2*)ie)[i];
    size_t ub = (size_t)u * FW2 + c2;
    __half2 ha = __floats2half2_rn(a.x, a.y);
    __half2 hb = __floats2half2_rn(b.x, b.y);
    __half2 hd = __floats2half2_rn(d.x, d.y);
    __half2 he = __floats2half2_rn(e.x, e.y);
    g_Xh[ub] = ha;       g_X0h[ub] = ha;
    g_Xh[ub + 32] = hb;  g_X0h[ub + 32] = hb;
    g_Xh[ub + 64] = hd;  g_X0h[ub + 64] = hd;
    size_t ib = (size_t)(NU + u) * FW2 + c2;
    g_Xh[ib] = he;       g_X0h[ib] = he;
}

// ---------------- projection GEMM (HMMA, register-prefetch pipelined) --------
// C(Mx64) = A(MxK) @ W(64xK)^T + bias ->  Xh + X0h fp16 item slices
// OUT_MODE 0: col offset 64 (v) ; OUT_MODE 1: col offset 128 (t)
#define LDA 40    // smem ld in halves
#define LDC2 20   // epilogue staging ld in floats (16 cols + pad)

template <int OUT_MODE>
__global__ void __launch_bounds__(256) k_wgemm_proj(const float* __restrict__ A, int M, int K,
                                                    const float* __restrict__ W,
                                                    const float* __restrict__ bias) {
    __shared__ __align__(16) char raw[128 * LDA * 2 + 64 * LDA * 2];   // 15360 B
    half*  As = (half*)raw;                   // [128][LDA]
    half*  Ws = (half*)(raw + 128 * LDA * 2); // [64][LDA]
    float* Cs = (float*)raw;                  // [128][LDC2] (overlaps A after K loop)

    int tid = threadIdx.x;
    int warp = tid >> 5;
    int rowBase = blockIdx.x * 128;

    wmma::fragment<wmma::accumulator, 16, 16, 16, float> acc[4];
#pragma unroll
    for (int nf = 0; nf < 4; ++nf) wmma::fill_fragment(acc[nf], 0.f);

    int lr = tid >> 1;               // 0..127 (A row)
    int lk = (tid & 1) * 16;         // 0/16   (A k base)
    bool rowOK = (rowBase + lr) < M;
    const float* Arow = A + (size_t)(rowBase + lr) * K + lk;

    float4 ra[4], rw[2];
    const float4 z4 = make_float4(0.f, 0.f, 0.f, 0.f);

#define LOAD_TILES(k0_)                                                     \
    {                                                                       \
        _Pragma("unroll")                                                   \
        for (int q = 0; q < 4; ++q)                                         \
            ra[q] = rowOK ? *(const float4*)(Arow + (k0_) + q * 4) : z4;    \
        _Pragma("unroll")                                                   \
        for (int it = 0; it < 2; ++it) {                                    \
            int f = tid + it * 256;                                         \
            int c = f >> 3;                                                 \
            int kq = (f & 7) * 4;                                           \
            rw[it] = *(const float4*)(W + (size_t)c * K + (k0_) + kq);      \
        }                                                                   \
    }

    LOAD_TILES(0);
    for (int k0 = 0; k0 < K; k0 += 32) {
        {
            half* da = As + lr * LDA + lk;
#pragma unroll
            for (int q = 0; q < 4; ++q) {
                *(half2*)(da + q * 4)     = __floats2half2_rn(ra[q].x, ra[q].y);
                *(half2*)(da + q * 4 + 2) = __floats2half2_rn(ra[q].z, ra[q].w);
            }
#pragma unroll
            for (int it = 0; it < 2; ++it) {
                int f = tid + it * 256;
                int c = f >> 3;
                int kq = (f & 7) * 4;
                half* dw = Ws + c * LDA + kq;
                *(half2*)(dw)     = __floats2half2_rn(rw[it].x, rw[it].y);
                *(half2*)(dw + 2) = __floats2half2_rn(rw[it].z, rw[it].w);
            }
        }
        __syncthreads();
        if (k0 + 32 < K) LOAD_TILES(k0 + 32);   // prefetch next while mma runs
#pragma unroll
        for (int kk = 0; kk < 32; kk += 16) {
            wmma::fragment<wmma::matrix_a, 16, 16, 16, half, wmma::row_major> af;
            wmma::load_matrix_sync(af, As + (warp * 16) * LDA + kk, LDA);
#pragma unroll
            for (int nf = 0; nf < 4; ++nf) {
                wmma::fragment<wmma::matrix_b, 16, 16, 16, half, wmma::col_major> bf;
                wmma::load_matrix_sync(bf, Ws + (nf * 16) * LDA + kk, LDA);
                wmma::mma_sync(acc[nf], af, bf, acc[nf]);
            }
        }
        __syncthreads();
    }

    // epilogue, staged 16 cols at a time through small smem
    int r = tid >> 1;
    int c8 = (tid & 1) * 8;
    int gr = rowBase + r;
    int coff = (OUT_MODE == 0) ? 64 : 128;
#pragma unroll
    for (int nf = 0; nf < 4; ++nf) {
        wmma::store_matrix_sync(Cs + (warp * 16) * LDC2, acc[nf], LDC2, wmma::mem_row_major);
        __syncthreads();
        if (gr < M) {
            const float* src = Cs + r * LDC2 + c8;
            int cbase = nf * 16 + c8;
            __half2 h[4];
#pragma unroll
            for (int q = 0; q < 4; ++q) {
                float vx = src[2 * q]     + __ldg(&bias[cbase + 2 * q]);
                float vy = src[2 * q + 1] + __ldg(&bias[cbase + 2 * q + 1]);
                h[q] = __floats2half2_rn(vx, vy);
            }
            uint4 u = make_uint4(h2u(h[0]), h2u(h[1]), h2u(h[2]), h2u(h[3]));
            size_t o = (size_t)(NU + gr) * FW2 + ((coff + cbase) >> 1);
            *(uint4*)(g_Xh + o)  = u;
            *(uint4*)(g_X0h + o) = u;
        }
        __syncthreads();
    }
}

// ---------------- dense layer GEMM: H = X @ W.T (fp16 in, fp16 out) ----------
// A = g_Xh viewed as [3*NN][64] halves; rows [rowStart, ...) bounded by grid
// HBUF selects the output buffer (0: g_Hh0, 1: g_Hh1)
#define LDH 72   // smem ld in halves

template <int HBUF>
__global__ void __launch_bounds__(256) k_wgemm_dense(const float* __restrict__ W, int rowStart) {
    const int M = 3 * NN;
    __half2* Hout = (HBUF == 0) ? g_Hh0 : g_Hh1;
    __shared__ __align__(16) char raw[128 * LDH * 2 + 64 * LDH * 2];   // 27648 B
    half*  As = (half*)raw;                   // [128][LDH]
    half*  Ws = (half*)(raw + 128 * LDH * 2); // [64][LDH]
    float* Cs = (float*)raw;                  // [128][LDC2]

    int tid = threadIdx.x;
    int warp = tid >> 5;
    int rowBase = rowStart + blockIdx.x * 128;
    const half* Ah = (const half*)g_Xh;

#pragma unroll
    for (int it = 0; it < 4; ++it) {
        int c = tid + it * 256;         // 0..1023
        int r = c >> 3;
        int o = (c & 7) * 8;            // half offset
        int gr = rowBase + r;
        uint4 v = make_uint4(0, 0, 0, 0);
        if (gr < M) v = *(const uint4*)(Ah + (size_t)gr * 64 + o);
        *(uint4*)(As + r * LDH + o) = v;
    }
    {
        int c = tid >> 2;
        int seg = (tid & 3) * 16;
        const float* wsrc = W + (size_t)c * 64 + seg;
        half* dw = Ws + c * LDH + seg;
#pragma unroll
        for (int q = 0; q < 4; ++q) {
            float4 v = *(const float4*)(wsrc + q * 4);
            *(half2*)(dw + q * 4)     = __floats2half2_rn(v.x, v.y);
            *(half2*)(dw + q * 4 + 2) = __floats2half2_rn(v.z, v.w);
        }
    }
    __syncthreads();

    wmma::fragment<wmma::accumulator, 16, 16, 16, float> acc[4];
#pragma unroll
    for (int nf = 0; nf < 4; ++nf) wmma::fill_fragment(acc[nf], 0.f);
#pragma unroll
    for (int kk = 0; kk < 64; kk += 16) {
        wmma::fragment<wmma::matrix_a, 16, 16, 16, half, wmma::row_major> af;
        wmma::load_matrix_sync(af, As + (warp * 16) * LDH + kk, LDH);
#pragma unroll
        for (int nf = 0; nf < 4; ++nf) {
            wmma::fragment<wmma::matrix_b, 16, 16, 16, half, wmma::col_major> bf;
            wmma::load_matrix_sync(bf, Ws + (nf * 16) * LDH + kk, LDH);
            wmma::mma_sync(acc[nf], af, bf, acc[nf]);
        }
    }
    __syncthreads();

    int r = tid >> 1;
    int c8 = (tid & 1) * 8;
    int gr = rowBase + r;
#pragma unroll
    for (int nf = 0; nf < 4; ++nf) {
        wmma::store_matrix_sync(Cs + (warp * 16) * LDC2, acc[nf], LDC2, wmma::mem_row_major);
        __syncthreads();
        if (gr < M) {
            const float* src = Cs + r * LDC2 + c8;
            __half2 h[4];
#pragma unroll
            for (int q = 0; q < 4; ++q)
                h[q] = __floats2half2_rn(src[2 * q], src[2 * q + 1]);
            uint4 u = make_uint4(h2u(h[0]), h2u(h[1]), h2u(h[2]), h2u(h[3]));
            *(uint4*)(Hout + (size_t)gr * 32 + ((nf * 16 + c8) >> 1)) = u;
        }
        __syncthreads();
    }
}

// ---------------- aggregation over fp16 H ------------------------------------
// x_new = dinv[dst]*(sum w*H[src] + dinv[dst]*H[dst]) + b
// FINAL=0: reads g_Hh0, Xh = x_new     (node range [nodeStart, nodeStart+nodeCnt))
// FINAL=1: reads g_Hh1, out[section] = (X0 + X1 + x_new)/3
#define AGG_STEP(e)                                                     \
    {                                                                   \
        int s_ = (e).x;                                                 \
        float w_ = __int_as_float((e).y);                               \
        size_t sb_ = (size_t)s_ * FW2 + lane;                           \
        float2 v0_ = __half22float2(__ldg(&Hh[sb_]));                   \
        float2 v1_ = __half22float2(__ldg(&Hh[sb_ + 32]));              \
        float2 v2_ = __half22float2(__ldg(&Hh[sb_ + 64]));              \
        a0x += w_ * v0_.x; a0y += w_ * v0_.y;                           \
        a1x += w_ * v1_.x; a1y += w_ * v1_.y;                           \
        a2x += w_ * v2_.x; a2y += w_ * v2_.y;                           \
    }

template <int FINAL>
__global__ void __launch_bounds__(256) k_agg(const float* __restrict__ bias,
                                             float* __restrict__ out,
                                             int nodeStart, int nodeCnt) {
    int warp = threadIdx.x >> 5;
    int lane = threadIdx.x & 31;
    int nidx = blockIdx.x * 8 + warp;
    if (nidx >= nodeCnt) return;
    int node = nodeStart + nidx;

    const __half2* Hh = (FINAL == 0) ? g_Hh0 : g_Hh1;

    float dn = g_dinv[node];
    size_t base = (size_t)node * FW2 + lane;

    // self-loop (weight dinv; outer dinv at end -> dinv^2)
    float2 h0 = __half22float2(__ldg(&Hh[base]));
    float2 h1 = __half22float2(__ldg(&Hh[base + 32]));
    float2 h2 = __half22float2(__ldg(&Hh[base + 64]));
    float a0x = dn * h0.x, a0y = dn * h0.y;
    float a1x = dn * h1.x, a1y = dn * h1.y;
    float a2x = dn * h2.x, a2y = dn * h2.y;

    int p = g_rowptr[node];
    int cnt = g_deg[node];

    int j = 0;
    for (; j + 8 <= cnt; j += 8) {
        int2 e0 = __ldg(&g_edges[p + j]);
        int2 e1 = __ldg(&g_edges[p + j + 1]);
        int2 e2 = __ldg(&g_edges[p + j + 2]);
        int2 e3 = __ldg(&g_edges[p + j + 3]);
        int2 e4 = __ldg(&g_edges[p + j + 4]);
        int2 e5 = __ldg(&g_edges[p + j + 5]);
        int2 e6 = __ldg(&g_edges[p + j + 6]);
        int2 e7 = __ldg(&g_edges[p + j + 7]);
        AGG_STEP(e0); AGG_STEP(e1); AGG_STEP(e2); AGG_STEP(e3);
        AGG_STEP(e4); AGG_STEP(e5); AGG_STEP(e6); AGG_STEP(e7);
    }
    for (; j < cnt; ++j) {
        int2 e = __ldg(&g_edges[p + j]);
        AGG_STEP(e);
    }

    float bx = __ldg(&bias[2 * lane]);
    float by = __ldg(&bias[2 * lane + 1]);
    float2 o0 = make_float2(a0x * dn + bx, a0y * dn + by);
    float2 o1 = make_float2(a1x * dn + bx, a1y * dn + by);
    float2 o2 = make_float2(a2x * dn + bx, a2y * dn + by);

    if (FINAL) {
        const float inv3 = 1.f / 3.f;
        int itm = (node >= NU) ? 1 : 0;
        int r = node - itm * NU;
        float2* O2 = (float2*)out;
        float2 x00 = __half22float2(g_X0h[base]);
        float2 x01 = __half22float2(g_X0h[base + 32]);
        float2 x02 = __half22float2(g_X0h[base + 64]);
        float2 x10 = __half22float2(g_Xh[base]);
        float2 x11 = __half22float2(g_Xh[base + 32]);
        float2 x12 = __half22float2(g_Xh[base + 64]);
        float2 r0 = make_float2((x00.x + x10.x + o0.x) * inv3, (x00.y + x10.y + o0.y) * inv3);
        float2 r1 = make_float2((x01.x + x11.x + o1.x) * inv3, (x01.y + x11.y + o1.y) * inv3);
        float2 r2 = make_float2((x02.x + x12.x + o2.x) * inv3, (x02.y + x12.y + o2.y) * inv3);
        O2[(size_t)(0 + itm) * (NU * 32) + (size_t)r * 32 + lane] = r0;
        O2[(size_t)(2 + itm) * (NU * 32) + (size_t)r * 32 + lane] = r1;
        O2[(size_t)(4 + itm) * (NU * 32) + (size_t)r * 32 + lane] = r2;
    } else {
        g_Xh[base]      = __floats2half2_rn(o0.x, o0.y);
        g_Xh[base + 32] = __floats2half2_rn(o1.x, o1.y);
        g_Xh[base + 64] = __floats2half2_rn(o2.x, o2.y);
    }
}

// ---------------- launch ------------------------------------------------------
extern "C" void kernel_launch(void* const* d_in, const int* in_sizes, int n_in,
                              void* d_out, int out_size) {
    const int* ei = (const int*)d_in[0];
    const float* v_feat = (const float*)d_in[1];
    const float* t_feat = (const float*)d_in[2];
    const float* user_emb = (const float*)d_in[3];
    const float* item_emb = (const float*)d_in[4];
    const float* user_emb_v = (const float*)d_in[5];
    const float* user_emb_t = (const float*)d_in[6];
    const float* W_v = (const float*)d_in[7];
    const float* b_v = (const float*)d_in[8];
    const float* W_t = (const float*)d_in[9];
    const float* b_t = (const float*)d_in[10];
    const float* W0 = (const float*)d_in[11];
    const float* b0 = (const float*)d_in[12];
    const float* W1 = (const float*)d_in[13];
    const float* b1 = (const float*)d_in[14];
    float* out = (float*)d_out;

    int E = in_sizes[0] / 2;
    if (E > EMAX) E = EMAX;

    // lazy infra (created on the uncaptured correctness call; reused thereafter)
    static cudaStream_t sT = nullptr, sG = nullptr;
    static cudaEvent_t evRoot = nullptr, evT = nullptr, evG = nullptr;
    static cudaEvent_t evA0A = nullptr, evD1A = nullptr;
    if (sT == nullptr) {
        cudaStreamCreateWithFlags(&sT, cudaStreamNonBlocking);
        cudaStreamCreateWithFlags(&sG, cudaStreamNonBlocking);
        cudaEventCreateWithFlags(&evRoot, cudaEventDisableTiming);
        cudaEventCreateWithFlags(&evT, cudaEventDisableTiming);
        cudaEventCreateWithFlags(&evG, cudaEventDisableTiming);
        cudaEventCreateWithFlags(&evA0A, cudaEventDisableTiming);
        cudaEventCreateWithFlags(&evD1A, cudaEventDisableTiming);
    }

    // fork side streams off the main (capture) stream
    cudaEventRecord(evRoot, 0);
    cudaStreamWaitEvent(sG, evRoot, 0);
    cudaStreamWaitEvent(sT, evRoot, 0);

    // sG: graph build (independent of everything else)
    k_deg_zero<<<(NN + 255) / 256, 256, 0, sG>>>();
    k_count<<<(E + 255) / 256, 256, 0, sG>>>(ei, E);
    k_scan1<<<NB_SCAN, 512, 0, sG>>>();
    k_scan2<<<1, 256, 0, sG>>>();
    k_scan3<<<NB_SCAN, 512, 0, sG>>>();
    k_fill<<<(E + 255) / 256, 256, 0, sG>>>(ei, E);
    cudaEventRecord(evG, sG);

    // sT: initX -> t projection -> dense-L0 user rows (all only need initX)
    k_initX<<<(NU * 32 + 255) / 256, 256, 0, sT>>>(user_emb, user_emb_v, user_emb_t, item_emb);
    k_wgemm_proj<1><<<(NU + 127) / 128, 256, 0, sT>>>(t_feat, NU, 768, W_t, b_t);
    k_wgemm_dense<0><<<DSPLIT / 128, 256, 0, sT>>>(W0, 0);
    cudaEventRecord(evT, sT);

    // main: v projection (big one) runs immediately
    k_wgemm_proj<0><<<(NU + 127) / 128, 256>>>(v_feat, NU, 2048, W_v, b_v);

    // join sT, then dense-L0 item rows
    cudaStreamWaitEvent(0, evT, 0);
    k_wgemm_dense<0><<<(3 * NN - DSPLIT + 127) / 128, 256>>>(W0, DSPLIT);

    // join graph build, then aggregate layer 0 (first half: nodes [0, NA))
    cudaStreamWaitEvent(0, evG, 0);
    k_agg<0><<<(NA + 7) / 8, 256>>>(b0, nullptr, 0, NA);
    cudaEventRecord(evA0A, 0);

    // sT: dense-L1 part A (rows [0, DSPLIT), X rows all produced by agg0 part A;
    //     writes g_Hh1 — no conflict with agg0 part B which reads g_Hh0)
    cudaStreamWaitEvent(sT, evA0A, 0);
    k_wgemm_dense<1><<<DSPLIT / 128, 256, 0, sT>>>(W1, 0);
    cudaEventRecord(evD1A, sT);

    // main: agg layer 0 second half (nodes [NA, NN)) — overlaps dense-L1 part A
    k_agg<0><<<(NN - NA + 7) / 8, 256>>>(b0, nullptr, NA, NN - NA);

    // join, dense-L1 part B, then final aggregation (fused output)
    cudaStreamWaitEvent(0, evD1A, 0);
    k_wgemm_dense<1><<<(3 * NN - DSPLIT + 127) / 128, 256>>>(W1, DSPLIT);
    k_agg<1><<<(NN + 7) / 8, 256>>>(b1, out, 0, NN);
}